// round 1
// baseline (speedup 1.0000x reference)
#include <cuda_runtime.h>
#include <math.h>
#include <stdint.h>

// Problem constants
constexpr int Bb   = 2;
constexpr int Nn   = 2048;
constexpr int Cc_  = 1024;
constexpr int Hh   = 16;
constexpr int HD   = 64;
constexpr int HID  = 4096;
constexpr int MTOK = Bb * Nn;            // 4096 token rows
constexpr float SCALE = 0.125f;          // 64^-0.5

// Scratch (static device allocations; no cudaMalloc allowed)
__device__ float g_qkv[(size_t)MTOK * 3 * Cc_];   // 48 MB
__device__ float g_ctx[(size_t)MTOK * Cc_];       // 16 MB
__device__ float g_res[(size_t)MTOK * Cc_];       // 16 MB  (attn-out -> residual)
__device__ float g_h  [(size_t)MTOK * HID];       // 64 MB
__device__ float g_mlp[(size_t)MTOK * Cc_];       // 16 MB

// ---------------------------------------------------------------------------
// SGEMM (NT): C[M,N] = A[M,K] @ B[N,K]^T (+bias) (+gelu)
// A row-major [M,K], B row-major [N,K] (both K-contiguous).
// 128x128 tile, BK=16, 256 threads, 8x8 per thread.
// Requires M%128==0, N%128==0, K%16==0 (true for all calls here).
// ---------------------------------------------------------------------------
__device__ __forceinline__ float gelu_exact(float v) {
    return 0.5f * v * (1.0f + erff(v * 0.70710678118654752f));
}

template<int EPI>   // 0 = bias(optional), 1 = bias + exact gelu
__global__ __launch_bounds__(256, 1)
void sgemm_nt(const float* __restrict__ A, const float* __restrict__ Bw,
              const float* __restrict__ bias, float* __restrict__ Co,
              int M, int N, int K)
{
    constexpr int BM = 128, BN = 128, BK = 16;
    __shared__ float As[BK][BM + 4];
    __shared__ float Bs[BK][BN + 4];

    const int tid = threadIdx.x;
    const int tx  = tid & 15;        // 0..15 (col group)
    const int ty  = tid >> 4;        // 0..15 (row group)
    const int m0  = blockIdx.y * BM;
    const int n0  = blockIdx.x * BN;

    // load mapping: 512 float4 per operand tile; 2 per thread
    const int lr = tid >> 2;         // 0..63 row (then +64)
    const int lc = (tid & 3) << 2;   // 0,4,8,12

    float acc[8][8];
    #pragma unroll
    for (int i = 0; i < 8; ++i)
        #pragma unroll
        for (int j = 0; j < 8; ++j) acc[i][j] = 0.f;

    for (int k0 = 0; k0 < K; k0 += BK) {
        #pragma unroll
        for (int h = 0; h < 2; ++h) {
            int r = lr + h * 64;
            float4 v = *(const float4*)(A + (size_t)(m0 + r) * K + k0 + lc);
            As[lc + 0][r] = v.x; As[lc + 1][r] = v.y;
            As[lc + 2][r] = v.z; As[lc + 3][r] = v.w;
        }
        #pragma unroll
        for (int h = 0; h < 2; ++h) {
            int r = lr + h * 64;
            float4 v = *(const float4*)(Bw + (size_t)(n0 + r) * K + k0 + lc);
            Bs[lc + 0][r] = v.x; Bs[lc + 1][r] = v.y;
            Bs[lc + 2][r] = v.z; Bs[lc + 3][r] = v.w;
        }
        __syncthreads();

        #pragma unroll
        for (int k = 0; k < BK; ++k) {
            float a[8], b[8];
            *(float4*)&a[0] = *(const float4*)&As[k][ty * 8 + 0];
            *(float4*)&a[4] = *(const float4*)&As[k][ty * 8 + 4];
            *(float4*)&b[0] = *(const float4*)&Bs[k][tx * 8 + 0];
            *(float4*)&b[4] = *(const float4*)&Bs[k][tx * 8 + 4];
            #pragma unroll
            for (int i = 0; i < 8; ++i)
                #pragma unroll
                for (int j = 0; j < 8; ++j)
                    acc[i][j] = fmaf(a[i], b[j], acc[i][j]);
        }
        __syncthreads();
    }

    // epilogue
    float bv[8];
    #pragma unroll
    for (int j = 0; j < 8; ++j)
        bv[j] = (bias != nullptr) ? bias[n0 + tx * 8 + j] : 0.f;

    #pragma unroll
    for (int i = 0; i < 8; ++i) {
        size_t m = (size_t)(m0 + ty * 8 + i);
        float* crow = Co + m * (size_t)N + n0 + tx * 8;
        #pragma unroll
        for (int j = 0; j < 8; j += 4) {
            float4 v;
            float t0 = acc[i][j + 0] + bv[j + 0];
            float t1 = acc[i][j + 1] + bv[j + 1];
            float t2 = acc[i][j + 2] + bv[j + 2];
            float t3 = acc[i][j + 3] + bv[j + 3];
            if (EPI == 1) {
                t0 = gelu_exact(t0); t1 = gelu_exact(t1);
                t2 = gelu_exact(t2); t3 = gelu_exact(t3);
            }
            v.x = t0; v.y = t1; v.z = t2; v.w = t3;
            *(float4*)(crow + j) = v;
        }
    }
}

// ---------------------------------------------------------------------------
// Flash attention (fp32). One thread = one q row. Block = 128 q rows.
// Grid: (N/128, H, B). K/V tiles of 32 rows in smem, float4 reads (broadcast).
// qkv layout per token row (stride 3C): [3, H, HD] -> q @ h*64, k @ C+h*64,
// v @ 2C+h*64. Output ctx layout: [B,N,C] with c = h*64+d.
// ---------------------------------------------------------------------------
__global__ __launch_bounds__(128, 2)
void flash_attn(const float* __restrict__ qkv, float* __restrict__ ctx)
{
    __shared__ float Ks[32][64];
    __shared__ float Vs[32][64];

    const int tid = threadIdx.x;
    const int qn  = blockIdx.x * 128 + tid;
    const int h   = blockIdx.y;
    const int b   = blockIdx.z;

    const size_t qbase = ((size_t)(b * Nn + qn)) * (3 * Cc_) + h * HD;

    float q[64], o[64];
    #pragma unroll
    for (int d = 0; d < 64; d += 4) {
        float4 v = *(const float4*)(qkv + qbase + d);
        q[d] = v.x; q[d+1] = v.y; q[d+2] = v.z; q[d+3] = v.w;
    }
    #pragma unroll
    for (int d = 0; d < 64; ++d) o[d] = 0.f;

    float m = -1e30f, l = 0.f;

    for (int k0 = 0; k0 < Nn; k0 += 32) {
        // cooperative K/V tile load: 512 float4 per tile, 4 per thread
        #pragma unroll
        for (int i = 0; i < 4; ++i) {
            int idx = tid + i * 128;           // 0..511
            int r = idx >> 4;
            int c = (idx & 15) << 2;
            size_t base = ((size_t)(b * Nn + k0 + r)) * (3 * Cc_) + h * HD + c;
            *(float4*)&Ks[r][c] = *(const float4*)(qkv + base + Cc_);
            *(float4*)&Vs[r][c] = *(const float4*)(qkv + base + 2 * Cc_);
        }
        __syncthreads();

        float s[32];
        #pragma unroll
        for (int j = 0; j < 32; ++j) {
            float a = 0.f;
            #pragma unroll
            for (int d = 0; d < 64; d += 4) {
                float4 kv = *(const float4*)&Ks[j][d];
                a = fmaf(q[d+0], kv.x, a);
                a = fmaf(q[d+1], kv.y, a);
                a = fmaf(q[d+2], kv.z, a);
                a = fmaf(q[d+3], kv.w, a);
            }
            s[j] = a * SCALE;
        }

        float tmax = s[0];
        #pragma unroll
        for (int j = 1; j < 32; ++j) tmax = fmaxf(tmax, s[j]);
        float nm   = fmaxf(m, tmax);
        float corr = __expf(m - nm);
        m = nm;
        l *= corr;
        #pragma unroll
        for (int d = 0; d < 64; ++d) o[d] *= corr;

        #pragma unroll
        for (int j = 0; j < 32; ++j) {
            float p = __expf(s[j] - m);
            l += p;
            #pragma unroll
            for (int d = 0; d < 64; d += 4) {
                float4 vv = *(const float4*)&Vs[j][d];
                o[d+0] = fmaf(p, vv.x, o[d+0]);
                o[d+1] = fmaf(p, vv.y, o[d+1]);
                o[d+2] = fmaf(p, vv.z, o[d+2]);
                o[d+3] = fmaf(p, vv.w, o[d+3]);
            }
        }
        __syncthreads();
    }

    const float inv = 1.f / l;
    const size_t obase = ((size_t)(b * Nn + qn)) * Cc_ + h * HD;
    #pragma unroll
    for (int d = 0; d < 64; d += 4) {
        float4 v;
        v.x = o[d+0] * inv; v.y = o[d+1] * inv;
        v.z = o[d+2] * inv; v.w = o[d+3] * inv;
        *(float4*)(ctx + obase + d) = v;
    }
}

// ---------------------------------------------------------------------------
// out[row] = res[row] + LayerNorm(x[row]) * w + b     (row length 1024)
// One block (256 threads) per row; each thread owns one float4.
// ---------------------------------------------------------------------------
__global__ __launch_bounds__(256)
void ln_residual(const float* __restrict__ x, const float* __restrict__ res,
                 const float* __restrict__ w, const float* __restrict__ bp,
                 float* __restrict__ out)
{
    __shared__ float red[256];
    const int row = blockIdx.x;
    const int tid = threadIdx.x;
    const size_t base = (size_t)row * Cc_;

    float4 v = *(const float4*)(x + base + tid * 4);
    float s = v.x + v.y + v.z + v.w;
    red[tid] = s;
    __syncthreads();
    #pragma unroll
    for (int off = 128; off > 0; off >>= 1) {
        if (tid < off) red[tid] += red[tid + off];
        __syncthreads();
    }
    const float mu = red[0] * (1.0f / Cc_);
    __syncthreads();

    float d0 = v.x - mu, d1 = v.y - mu, d2 = v.z - mu, d3 = v.w - mu;
    red[tid] = d0*d0 + d1*d1 + d2*d2 + d3*d3;
    __syncthreads();
    #pragma unroll
    for (int off = 128; off > 0; off >>= 1) {
        if (tid < off) red[tid] += red[tid + off];
        __syncthreads();
    }
    const float var  = red[0] * (1.0f / Cc_);
    const float rstd = rsqrtf(var + 1e-5f);

    float4 rv = *(const float4*)(res + base + tid * 4);
    float4 wv = *(const float4*)(w + tid * 4);
    float4 bv = *(const float4*)(bp + tid * 4);
    float4 ov;
    ov.x = rv.x + d0 * rstd * wv.x + bv.x;
    ov.y = rv.y + d1 * rstd * wv.y + bv.y;
    ov.z = rv.z + d2 * rstd * wv.z + bv.z;
    ov.w = rv.w + d3 * rstd * wv.w + bv.w;
    *(float4*)(out + base + tid * 4) = ov;
}

// ---------------------------------------------------------------------------
// Launch
// ---------------------------------------------------------------------------
extern "C" void kernel_launch(void* const* d_in, const int* in_sizes, int n_in,
                              void* d_out, int out_size)
{
    const float* x      = (const float*)d_in[0];
    const float* qkv_w  = (const float*)d_in[1];
    const float* proj_w = (const float*)d_in[2];
    const float* proj_b = (const float*)d_in[3];
    const float* ln1_w  = (const float*)d_in[4];
    const float* ln1_b  = (const float*)d_in[5];
    const float* fc1_w  = (const float*)d_in[6];
    const float* fc1_b  = (const float*)d_in[7];
    const float* fc2_w  = (const float*)d_in[8];
    const float* fc2_b  = (const float*)d_in[9];
    const float* ln2_w  = (const float*)d_in[10];
    const float* ln2_b  = (const float*)d_in[11];
    float* out = (float*)d_out;

    float *qkv, *ctx, *res, *hbuf, *mlp;
    cudaGetSymbolAddress((void**)&qkv,  g_qkv);
    cudaGetSymbolAddress((void**)&ctx,  g_ctx);
    cudaGetSymbolAddress((void**)&res,  g_res);
    cudaGetSymbolAddress((void**)&hbuf, g_h);
    cudaGetSymbolAddress((void**)&mlp,  g_mlp);

    // 1) qkv = x @ qkv_w^T            [4096, 3072]
    sgemm_nt<0><<<dim3(3 * Cc_ / 128, MTOK / 128), 256>>>(x, qkv_w, nullptr, qkv,
                                                          MTOK, 3 * Cc_, Cc_);
    // 2) attention -> ctx             [4096, 1024]
    flash_attn<<<dim3(Nn / 128, Hh, Bb), 128>>>(qkv, ctx);

    // 3) res = ctx @ proj_w^T + proj_b
    sgemm_nt<0><<<dim3(Cc_ / 128, MTOK / 128), 256>>>(ctx, proj_w, proj_b, res,
                                                      MTOK, Cc_, Cc_);
    // 4) res = res + LN(res)  (in place)
    ln_residual<<<MTOK, 256>>>(res, res, ln1_w, ln1_b, res);

    // 5) h = gelu(res @ fc1_w^T + fc1_b)   [4096, 4096]
    sgemm_nt<1><<<dim3(HID / 128, MTOK / 128), 256>>>(res, fc1_w, fc1_b, hbuf,
                                                      MTOK, HID, Cc_);
    // 6) mlp = h @ fc2_w^T + fc2_b
    sgemm_nt<0><<<dim3(Cc_ / 128, MTOK / 128), 256>>>(hbuf, fc2_w, fc2_b, mlp,
                                                      MTOK, Cc_, HID);
    // 7) out = res + LN(mlp)
    ln_residual<<<MTOK, 256>>>(mlp, res, ln2_w, ln2_b, out);
}

// round 3
// speedup vs baseline: 1.8559x; 1.8559x over previous
#include <cuda_runtime.h>
#include <math.h>
#include <stdint.h>

// Problem constants
constexpr int Bb   = 2;
constexpr int Nn   = 2048;
constexpr int Cc_  = 1024;
constexpr int Hh   = 16;
constexpr int HD   = 64;
constexpr int HID  = 4096;
constexpr int MTOK = Bb * Nn;            // 4096 token rows
constexpr float SCALE = 0.125f;          // 64^-0.5

// Scratch (static device allocations; no cudaMalloc allowed)
__device__ float g_qkv[(size_t)MTOK * 3 * Cc_];   // 48 MB
__device__ float g_ctx[(size_t)MTOK * Cc_];       // 16 MB
__device__ float g_res[(size_t)MTOK * Cc_];       // 16 MB
__device__ float g_h  [(size_t)MTOK * HID];       // 64 MB
__device__ float g_mlp[(size_t)MTOK * Cc_];       // 16 MB

// ===========================================================================
// helpers
// ===========================================================================
__device__ __forceinline__ uint32_t smem_u32(const void* p) {
    uint32_t a;
    asm("{ .reg .u64 t; cvta.to.shared.u64 t, %1; cvt.u32.u64 %0, t; }"
        : "=r"(a) : "l"(p));
    return a;
}
__device__ __forceinline__ void cp_async16(uint32_t dst, const void* src) {
    asm volatile("cp.async.cg.shared.global [%0], [%1], 16;"
                 :: "r"(dst), "l"(src));
}
#define CP_COMMIT() asm volatile("cp.async.commit_group;" ::: "memory")
#define CP_WAIT1()  asm volatile("cp.async.wait_group 1;" ::: "memory")

__device__ __forceinline__ uint32_t f2tf32(float f) {
    uint32_t u;
    asm("cvt.rna.tf32.f32 %0, %1;" : "=r"(u) : "f"(f));
    return u;
}

// mma.sync m16n8k8 tf32, fp32 accumulate
__device__ __forceinline__ void mma_tf32(float* c, const uint32_t* a,
                                         const uint32_t* b) {
    asm volatile(
        "mma.sync.aligned.m16n8k8.row.col.f32.tf32.tf32.f32 "
        "{%0,%1,%2,%3}, {%4,%5,%6,%7}, {%8,%9}, {%0,%1,%2,%3};"
        : "+f"(c[0]), "+f"(c[1]), "+f"(c[2]), "+f"(c[3])
        : "r"(a[0]), "r"(a[1]), "r"(a[2]), "r"(a[3]),
          "r"(b[0]), "r"(b[1]));
}

__device__ __forceinline__ float gelu_exact(float v) {
    return 0.5f * v * (1.0f + erff(v * 0.70710678118654752f));
}

// ===========================================================================
// tf32 mma.sync GEMM (NT): C[M,N] = A[M,K] @ B[N,K]^T (+bias)(+gelu)
// BM=BN=128, BK=32, 256 threads (8 warps, 2x4), warp tile 64x32.
// Smem: row-major [rows][BK+4] (pitch 36 floats) -> conflict-free frag loads.
// Requires M%128==0, N%128==0, K%32==0.
// ===========================================================================
constexpr int GBM = 128, GBN = 128, GBK = 32;
constexpr int GPITCH = GBK + 4;                     // 36 floats = 144 B
constexpr int STAGE_F = GBM * GPITCH;               // floats per operand stage
constexpr int GEMM_SMEM = 2 * 2 * STAGE_F * 4;      // 73728 B

template<int EPI>   // 0 = bias(optional), 1 = bias + exact gelu
__global__ __launch_bounds__(256, 2)
void tf32_gemm(const float* __restrict__ A, const float* __restrict__ Bw,
               const float* __restrict__ bias, float* __restrict__ Co,
               int M, int N, int K)
{
    extern __shared__ float smem[];
    float* As = smem;                       // 2 stages
    float* Bs = smem + 2 * STAGE_F;         // 2 stages
    const uint32_t As_u = smem_u32(As);
    const uint32_t Bs_u = smem_u32(Bs);

    const int tid = threadIdx.x;
    const int wid = tid >> 5;
    const int lid = tid & 31;
    const int g   = lid >> 2;      // group id  0..7
    const int tig = lid & 3;       // thread-in-group 0..3
    const int wm  = (wid & 1) * 64;
    const int wn  = (wid >> 1) * 32;
    const int m0  = blockIdx.y * GBM;
    const int n0  = blockIdx.x * GBN;
    const int NC  = K / GBK;

    float acc[4][4][4];
    #pragma unroll
    for (int i = 0; i < 4; ++i)
        #pragma unroll
        for (int j = 0; j < 4; ++j)
            #pragma unroll
            for (int t = 0; t < 4; ++t) acc[i][j][t] = 0.f;

    // cooperative load: tile = 128 rows x 8 16B-chunks = 1024 chunks; 4/thread
    auto load_chunk = [&](int kc, int st) {
        const int k0f = kc * GBK;
        const uint32_t abase = As_u + st * STAGE_F * 4;
        const uint32_t bbase = Bs_u + st * STAGE_F * 4;
        #pragma unroll
        for (int t = 0; t < 4; ++t) {
            int idx = tid + t * 256;
            int r   = idx >> 3;
            int c   = idx & 7;                 // 16B chunk within 128B row
            uint32_t off = (uint32_t)(r * (GPITCH * 4) + c * 16);
            cp_async16(abase + off, A + (size_t)(m0 + r) * K + k0f + c * 4);
            cp_async16(bbase + off, Bw + (size_t)(n0 + r) * K + k0f + c * 4);
        }
        CP_COMMIT();
    };

    load_chunk(0, 0);
    load_chunk(1, 1);

    for (int i = 0; i < NC; ++i) {
        const int st = i & 1;
        CP_WAIT1();
        __syncthreads();

        const float* Ast = As + st * STAGE_F;
        const float* Bst = Bs + st * STAGE_F;

        #pragma unroll
        for (int kk = 0; kk < 4; ++kk) {
            const int kc = kk * 8;
            uint32_t af[4][4], bf[4][2];
            #pragma unroll
            for (int mf = 0; mf < 4; ++mf) {
                const float* r0 = Ast + (wm + mf * 16 + g) * GPITCH + kc;
                const float* r1 = r0 + 8 * GPITCH;
                af[mf][0] = f2tf32(r0[tig]);
                af[mf][1] = f2tf32(r1[tig]);
                af[mf][2] = f2tf32(r0[tig + 4]);
                af[mf][3] = f2tf32(r1[tig + 4]);
            }
            #pragma unroll
            for (int nf = 0; nf < 4; ++nf) {
                const float* rb = Bst + (wn + nf * 8 + g) * GPITCH + kc;
                bf[nf][0] = f2tf32(rb[tig]);
                bf[nf][1] = f2tf32(rb[tig + 4]);
            }
            #pragma unroll
            for (int mf = 0; mf < 4; ++mf)
                #pragma unroll
                for (int nf = 0; nf < 4; ++nf)
                    mma_tf32(acc[mf][nf], af[mf], bf[nf]);
        }

        __syncthreads();
        if (i + 2 < NC) load_chunk(i + 2, st);
        else            CP_COMMIT();          // keep group count consistent
    }

    // ---- epilogue ----
    #pragma unroll
    for (int mf = 0; mf < 4; ++mf) {
        const int r0 = m0 + wm + mf * 16 + g;
        const int r1 = r0 + 8;
        #pragma unroll
        for (int nf = 0; nf < 4; ++nf) {
            const int col = n0 + wn + nf * 8 + tig * 2;
            float b0 = 0.f, b1 = 0.f;
            if (bias) { b0 = bias[col]; b1 = bias[col + 1]; }
            float t0 = acc[mf][nf][0] + b0;
            float t1 = acc[mf][nf][1] + b1;
            float t2 = acc[mf][nf][2] + b0;
            float t3 = acc[mf][nf][3] + b1;
            if (EPI == 1) {
                t0 = gelu_exact(t0); t1 = gelu_exact(t1);
                t2 = gelu_exact(t2); t3 = gelu_exact(t3);
            }
            float2 v0; v0.x = t0; v0.y = t1;
            float2 v1; v1.x = t2; v1.y = t3;
            *(float2*)(Co + (size_t)r0 * N + col) = v0;
            *(float2*)(Co + (size_t)r1 * N + col) = v1;
        }
    }
}

// ---------------------------------------------------------------------------
// Flash attention (fp32). One thread = one q row. Block = 128 q rows.
// ---------------------------------------------------------------------------
__global__ __launch_bounds__(128, 2)
void flash_attn(const float* __restrict__ qkv, float* __restrict__ ctx)
{
    __shared__ float Ks[32][64];
    __shared__ float Vs[32][64];

    const int tid = threadIdx.x;
    const int qn  = blockIdx.x * 128 + tid;
    const int h   = blockIdx.y;
    const int b   = blockIdx.z;

    const size_t qbase = ((size_t)(b * Nn + qn)) * (3 * Cc_) + h * HD;

    float q[64], o[64];
    #pragma unroll
    for (int d = 0; d < 64; d += 4) {
        float4 v = *(const float4*)(qkv + qbase + d);
        q[d] = v.x; q[d+1] = v.y; q[d+2] = v.z; q[d+3] = v.w;
    }
    #pragma unroll
    for (int d = 0; d < 64; ++d) o[d] = 0.f;

    float m = -1e30f, l = 0.f;

    for (int k0 = 0; k0 < Nn; k0 += 32) {
        #pragma unroll
        for (int i = 0; i < 4; ++i) {
            int idx = tid + i * 128;
            int r = idx >> 4;
            int c = (idx & 15) << 2;
            size_t base = ((size_t)(b * Nn + k0 + r)) * (3 * Cc_) + h * HD + c;
            *(float4*)&Ks[r][c] = *(const float4*)(qkv + base + Cc_);
            *(float4*)&Vs[r][c] = *(const float4*)(qkv + base + 2 * Cc_);
        }
        __syncthreads();

        float s[32];
        #pragma unroll
        for (int j = 0; j < 32; ++j) {
            float a = 0.f;
            #pragma unroll
            for (int d = 0; d < 64; d += 4) {
                float4 kv = *(const float4*)&Ks[j][d];
                a = fmaf(q[d+0], kv.x, a);
                a = fmaf(q[d+1], kv.y, a);
                a = fmaf(q[d+2], kv.z, a);
                a = fmaf(q[d+3], kv.w, a);
            }
            s[j] = a * SCALE;
        }

        float tmax = s[0];
        #pragma unroll
        for (int j = 1; j < 32; ++j) tmax = fmaxf(tmax, s[j]);
        float nm   = fmaxf(m, tmax);
        float corr = __expf(m - nm);
        m = nm;
        l *= corr;
        #pragma unroll
        for (int d = 0; d < 64; ++d) o[d] *= corr;

        #pragma unroll
        for (int j = 0; j < 32; ++j) {
            float p = __expf(s[j] - m);
            l += p;
            #pragma unroll
            for (int d = 0; d < 64; d += 4) {
                float4 vv = *(const float4*)&Vs[j][d];
                o[d+0] = fmaf(p, vv.x, o[d+0]);
                o[d+1] = fmaf(p, vv.y, o[d+1]);
                o[d+2] = fmaf(p, vv.z, o[d+2]);
                o[d+3] = fmaf(p, vv.w, o[d+3]);
            }
        }
        __syncthreads();
    }

    const float inv = 1.f / l;
    const size_t obase = ((size_t)(b * Nn + qn)) * Cc_ + h * HD;
    #pragma unroll
    for (int d = 0; d < 64; d += 4) {
        float4 v;
        v.x = o[d+0] * inv; v.y = o[d+1] * inv;
        v.z = o[d+2] * inv; v.w = o[d+3] * inv;
        *(float4*)(ctx + obase + d) = v;
    }
}

// ---------------------------------------------------------------------------
// out[row] = res[row] + LayerNorm(x[row]) * w + b     (row length 1024)
// ---------------------------------------------------------------------------
__global__ __launch_bounds__(256)
void ln_residual(const float* __restrict__ x, const float* __restrict__ res,
                 const float* __restrict__ w, const float* __restrict__ bp,
                 float* __restrict__ out)
{
    __shared__ float red[256];
    const int row = blockIdx.x;
    const int tid = threadIdx.x;
    const size_t base = (size_t)row * Cc_;

    float4 v = *(const float4*)(x + base + tid * 4);
    float s = v.x + v.y + v.z + v.w;
    red[tid] = s;
    __syncthreads();
    #pragma unroll
    for (int off = 128; off > 0; off >>= 1) {
        if (tid < off) red[tid] += red[tid + off];
        __syncthreads();
    }
    const float mu = red[0] * (1.0f / Cc_);
    __syncthreads();

    float d0 = v.x - mu, d1 = v.y - mu, d2 = v.z - mu, d3 = v.w - mu;
    red[tid] = d0*d0 + d1*d1 + d2*d2 + d3*d3;
    __syncthreads();
    #pragma unroll
    for (int off = 128; off > 0; off >>= 1) {
        if (tid < off) red[tid] += red[tid + off];
        __syncthreads();
    }
    const float var  = red[0] * (1.0f / Cc_);
    const float rstd = rsqrtf(var + 1e-5f);

    float4 rv = *(const float4*)(res + base + tid * 4);
    float4 wv = *(const float4*)(w + tid * 4);
    float4 bv = *(const float4*)(bp + tid * 4);
    float4 ov;
    ov.x = rv.x + d0 * rstd * wv.x + bv.x;
    ov.y = rv.y + d1 * rstd * wv.y + bv.y;
    ov.z = rv.z + d2 * rstd * wv.z + bv.z;
    ov.w = rv.w + d3 * rstd * wv.w + bv.w;
    *(float4*)(out + base + tid * 4) = ov;
}

// ---------------------------------------------------------------------------
// Launch
// ---------------------------------------------------------------------------
extern "C" void kernel_launch(void* const* d_in, const int* in_sizes, int n_in,
                              void* d_out, int out_size)
{
    const float* x      = (const float*)d_in[0];
    const float* qkv_w  = (const float*)d_in[1];
    const float* proj_w = (const float*)d_in[2];
    const float* proj_b = (const float*)d_in[3];
    const float* ln1_w  = (const float*)d_in[4];
    const float* ln1_b  = (const float*)d_in[5];
    const float* fc1_w  = (const float*)d_in[6];
    const float* fc1_b  = (const float*)d_in[7];
    const float* fc2_w  = (const float*)d_in[8];
    const float* fc2_b  = (const float*)d_in[9];
    const float* ln2_w  = (const float*)d_in[10];
    const float* ln2_b  = (const float*)d_in[11];
    float* out = (float*)d_out;

    float *qkv, *ctx, *res, *hbuf, *mlp;
    cudaGetSymbolAddress((void**)&qkv,  g_qkv);
    cudaGetSymbolAddress((void**)&ctx,  g_ctx);
    cudaGetSymbolAddress((void**)&res,  g_res);
    cudaGetSymbolAddress((void**)&hbuf, g_h);
    cudaGetSymbolAddress((void**)&mlp,  g_mlp);

    cudaFuncSetAttribute(tf32_gemm<0>,
        cudaFuncAttributeMaxDynamicSharedMemorySize, GEMM_SMEM);
    cudaFuncSetAttribute(tf32_gemm<1>,
        cudaFuncAttributeMaxDynamicSharedMemorySize, GEMM_SMEM);

    // 1) qkv = x @ qkv_w^T            [4096, 3072]
    tf32_gemm<0><<<dim3(3 * Cc_ / GBN, MTOK / GBM), 256, GEMM_SMEM>>>(
        x, qkv_w, nullptr, qkv, MTOK, 3 * Cc_, Cc_);
    // 2) attention -> ctx             [4096, 1024]
    flash_attn<<<dim3(Nn / 128, Hh, Bb), 128>>>(qkv, ctx);
    // 3) res = ctx @ proj_w^T + proj_b
    tf32_gemm<0><<<dim3(Cc_ / GBN, MTOK / GBM), 256, GEMM_SMEM>>>(
        ctx, proj_w, proj_b, res, MTOK, Cc_, Cc_);
    // 4) res = res + LN(res)  (in place)
    ln_residual<<<MTOK, 256>>>(res, res, ln1_w, ln1_b, res);
    // 5) h = gelu(res @ fc1_w^T + fc1_b)   [4096, 4096]
    tf32_gemm<1><<<dim3(HID / GBN, MTOK / GBM), 256, GEMM_SMEM>>>(
        res, fc1_w, fc1_b, hbuf, MTOK, HID, Cc_);
    // 6) mlp = h @ fc2_w^T + fc2_b
    tf32_gemm<0><<<dim3(Cc_ / GBN, MTOK / GBM), 256, GEMM_SMEM>>>(
        hbuf, fc2_w, fc2_b, mlp, MTOK, Cc_, HID);
    // 7) out = res + LN(mlp)
    ln_residual<<<MTOK, 256>>>(mlp, res, ln2_w, ln2_b, out);
}

// round 4
// speedup vs baseline: 3.1333x; 1.6883x over previous
#include <cuda_runtime.h>
#include <math.h>
#include <stdint.h>

// Problem constants
constexpr int Bb   = 2;
constexpr int Nn   = 2048;
constexpr int Cc_  = 1024;
constexpr int Hh   = 16;
constexpr int HD   = 64;
constexpr int HID  = 4096;
constexpr int MTOK = Bb * Nn;            // 4096 token rows
constexpr float SCALE = 0.125f;          // 64^-0.5

// Scratch (static device allocations; no cudaMalloc allowed)
__device__ float g_qkv[(size_t)MTOK * 3 * Cc_];   // 48 MB
__device__ float g_ctx[(size_t)MTOK * Cc_];       // 16 MB
__device__ float g_res[(size_t)MTOK * Cc_];       // 16 MB
__device__ float g_h  [(size_t)MTOK * HID];       // 64 MB
__device__ float g_mlp[(size_t)MTOK * Cc_];       // 16 MB

// ===========================================================================
// helpers
// ===========================================================================
__device__ __forceinline__ uint32_t smem_u32(const void* p) {
    uint32_t a;
    asm("{ .reg .u64 t; cvta.to.shared.u64 t, %1; cvt.u32.u64 %0, t; }"
        : "=r"(a) : "l"(p));
    return a;
}
__device__ __forceinline__ void cp_async16(uint32_t dst, const void* src) {
    asm volatile("cp.async.cg.shared.global [%0], [%1], 16;"
                 :: "r"(dst), "l"(src));
}
#define CP_COMMIT() asm volatile("cp.async.commit_group;" ::: "memory")
#define CP_WAIT1()  asm volatile("cp.async.wait_group 1;" ::: "memory")
#define CP_WAIT2()  asm volatile("cp.async.wait_group 2;" ::: "memory")

__device__ __forceinline__ uint32_t f2tf32(float f) {
    uint32_t u;
    asm("cvt.rna.tf32.f32 %0, %1;" : "=r"(u) : "f"(f));
    return u;
}
__device__ __forceinline__ float f2tf32f(float f) {
    return __uint_as_float(f2tf32(f));
}

// mma.sync m16n8k8 tf32, fp32 accumulate
__device__ __forceinline__ void mma_tf32(float* c, const uint32_t* a,
                                         const uint32_t* b) {
    asm volatile(
        "mma.sync.aligned.m16n8k8.row.col.f32.tf32.tf32.f32 "
        "{%0,%1,%2,%3}, {%4,%5,%6,%7}, {%8,%9}, {%0,%1,%2,%3};"
        : "+f"(c[0]), "+f"(c[1]), "+f"(c[2]), "+f"(c[3])
        : "r"(a[0]), "r"(a[1]), "r"(a[2]), "r"(a[3]),
          "r"(b[0]), "r"(b[1]));
}

__device__ __forceinline__ float gelu_exact(float v) {
    return 0.5f * v * (1.0f + erff(v * 0.70710678118654752f));
}

// ===========================================================================
// tf32 mma.sync GEMM (NT): C[M,N] = A[M,K] @ B[N,K]^T (+bias)(+gelu)
// (unchanged from R3 — validated)
// ===========================================================================
constexpr int GBM = 128, GBN = 128, GBK = 32;
constexpr int GPITCH = GBK + 4;                     // 36 floats
constexpr int STAGE_F = GBM * GPITCH;
constexpr int GEMM_SMEM = 2 * 2 * STAGE_F * 4;      // 73728 B

template<int EPI>
__global__ __launch_bounds__(256, 2)
void tf32_gemm(const float* __restrict__ A, const float* __restrict__ Bw,
               const float* __restrict__ bias, float* __restrict__ Co,
               int M, int N, int K)
{
    extern __shared__ float smem[];
    float* As = smem;
    float* Bs = smem + 2 * STAGE_F;
    const uint32_t As_u = smem_u32(As);
    const uint32_t Bs_u = smem_u32(Bs);

    const int tid = threadIdx.x;
    const int wid = tid >> 5;
    const int lid = tid & 31;
    const int g   = lid >> 2;
    const int tig = lid & 3;
    const int wm  = (wid & 1) * 64;
    const int wn  = (wid >> 1) * 32;
    const int m0  = blockIdx.y * GBM;
    const int n0  = blockIdx.x * GBN;
    const int NC  = K / GBK;

    float acc[4][4][4];
    #pragma unroll
    for (int i = 0; i < 4; ++i)
        #pragma unroll
        for (int j = 0; j < 4; ++j)
            #pragma unroll
            for (int t = 0; t < 4; ++t) acc[i][j][t] = 0.f;

    auto load_chunk = [&](int kc, int st) {
        const int k0f = kc * GBK;
        const uint32_t abase = As_u + st * STAGE_F * 4;
        const uint32_t bbase = Bs_u + st * STAGE_F * 4;
        #pragma unroll
        for (int t = 0; t < 4; ++t) {
            int idx = tid + t * 256;
            int r   = idx >> 3;
            int c   = idx & 7;
            uint32_t off = (uint32_t)(r * (GPITCH * 4) + c * 16);
            cp_async16(abase + off, A + (size_t)(m0 + r) * K + k0f + c * 4);
            cp_async16(bbase + off, Bw + (size_t)(n0 + r) * K + k0f + c * 4);
        }
        CP_COMMIT();
    };

    load_chunk(0, 0);
    load_chunk(1, 1);

    for (int i = 0; i < NC; ++i) {
        const int st = i & 1;
        CP_WAIT1();
        __syncthreads();

        const float* Ast = As + st * STAGE_F;
        const float* Bst = Bs + st * STAGE_F;

        #pragma unroll
        for (int kk = 0; kk < 4; ++kk) {
            const int kc = kk * 8;
            uint32_t af[4][4], bf[4][2];
            #pragma unroll
            for (int mf = 0; mf < 4; ++mf) {
                const float* r0 = Ast + (wm + mf * 16 + g) * GPITCH + kc;
                const float* r1 = r0 + 8 * GPITCH;
                af[mf][0] = f2tf32(r0[tig]);
                af[mf][1] = f2tf32(r1[tig]);
                af[mf][2] = f2tf32(r0[tig + 4]);
                af[mf][3] = f2tf32(r1[tig + 4]);
            }
            #pragma unroll
            for (int nf = 0; nf < 4; ++nf) {
                const float* rb = Bst + (wn + nf * 8 + g) * GPITCH + kc;
                bf[nf][0] = f2tf32(rb[tig]);
                bf[nf][1] = f2tf32(rb[tig + 4]);
            }
            #pragma unroll
            for (int mf = 0; mf < 4; ++mf)
                #pragma unroll
                for (int nf = 0; nf < 4; ++nf)
                    mma_tf32(acc[mf][nf], af[mf], bf[nf]);
        }

        __syncthreads();
        if (i + 2 < NC) load_chunk(i + 2, st);
        else            CP_COMMIT();
    }

    #pragma unroll
    for (int mf = 0; mf < 4; ++mf) {
        const int r0 = m0 + wm + mf * 16 + g;
        const int r1 = r0 + 8;
        #pragma unroll
        for (int nf = 0; nf < 4; ++nf) {
            const int col = n0 + wn + nf * 8 + tig * 2;
            float b0 = 0.f, b1 = 0.f;
            if (bias) { b0 = bias[col]; b1 = bias[col + 1]; }
            float t0 = acc[mf][nf][0] + b0;
            float t1 = acc[mf][nf][1] + b1;
            float t2 = acc[mf][nf][2] + b0;
            float t3 = acc[mf][nf][3] + b1;
            if (EPI == 1) {
                t0 = gelu_exact(t0); t1 = gelu_exact(t1);
                t2 = gelu_exact(t2); t3 = gelu_exact(t3);
            }
            float2 v0; v0.x = t0; v0.y = t1;
            float2 v1; v1.x = t2; v1.y = t3;
            *(float2*)(Co + (size_t)r0 * N + col) = v0;
            *(float2*)(Co + (size_t)r1 * N + col) = v1;
        }
    }
}

// ===========================================================================
// Flash attention via mma.sync tf32.
// 128 q rows per CTA (8 warps x 16 rows), 64-key tiles, double-buffered.
// ===========================================================================
constexpr int AQ  = 128;
constexpr int AKT = 64;
constexpr int APi = 68;                                // pitch (floats)
constexpr int A_KS = AQ * APi;                         // Q tile floats
constexpr int A_VS = A_KS + 2 * AKT * APi;
constexpr int ATT_SMEM = (A_VS + 2 * AKT * APi) * 4;   // 104448 B

__global__ __launch_bounds__(256, 1)
void attn_mma(const float* __restrict__ qkv, float* __restrict__ ctx)
{
    extern __shared__ float sm[];
    float* Qs = sm;
    float* Ks = sm + A_KS;
    float* Vs = sm + A_VS;
    const uint32_t Qs_u = smem_u32(Qs);
    const uint32_t Ks_u = smem_u32(Ks);
    const uint32_t Vs_u = smem_u32(Vs);

    const int tid = threadIdx.x;
    const int wid = tid >> 5;
    const int lid = tid & 31;
    const int g   = lid >> 2;
    const int tig = lid & 3;
    const int q0  = blockIdx.x * AQ;
    const int h   = blockIdx.y;
    const int b   = blockIdx.z;
    const int wq  = wid * 16;

    const size_t tok0 = (size_t)(b * Nn);
    const int hoff = h * HD;

    // group 0: Q tile (128 x 64)
    #pragma unroll
    for (int t = 0; t < 8; ++t) {
        int idx = tid + t * 256;
        int r = idx >> 4, c = idx & 15;
        cp_async16(Qs_u + (uint32_t)(r * APi + c * 4) * 4,
                   qkv + (tok0 + q0 + r) * (3 * Cc_) + hoff + c * 4);
    }
    CP_COMMIT();

    auto load_tile = [&](int kt, int st) {
        const int k0 = kt * AKT;
        const uint32_t kb = Ks_u + (uint32_t)(st * AKT * APi) * 4;
        const uint32_t vb = Vs_u + (uint32_t)(st * AKT * APi) * 4;
        #pragma unroll
        for (int t = 0; t < 4; ++t) {
            int idx = tid + t * 256;
            int r = idx >> 4, c = idx & 15;
            const float* src = qkv + (tok0 + k0 + r) * (3 * Cc_) + Cc_ + hoff + c * 4;
            uint32_t off = (uint32_t)(r * APi + c * 4) * 4;
            cp_async16(kb + off, src);
            cp_async16(vb + off, src + Cc_);
        }
        CP_COMMIT();
    };
    load_tile(0, 0);
    load_tile(1, 1);

    // Q ready (tiles 0/1 may still be pending)
    CP_WAIT2();
    __syncthreads();
    // cvt Q in place (fold SCALE)
    #pragma unroll
    for (int t = 0; t < 8; ++t) {
        int idx = tid + t * 256;
        int r = idx >> 4, c = idx & 15;
        float4* p = (float4*)(Qs + r * APi + c * 4);
        float4 v = *p;
        v.x = f2tf32f(v.x * SCALE); v.y = f2tf32f(v.y * SCALE);
        v.z = f2tf32f(v.z * SCALE); v.w = f2tf32f(v.w * SCALE);
        *p = v;
    }
    __syncthreads();

    // Q fragments (16 rows x 64 d) per warp
    uint32_t qf[8][4];
    #pragma unroll
    for (int kk = 0; kk < 8; ++kk) {
        const float* r0 = Qs + (wq + g) * APi + kk * 8;
        qf[kk][0] = __float_as_uint(r0[tig]);
        qf[kk][1] = __float_as_uint(r0[8 * APi + tig]);
        qf[kk][2] = __float_as_uint(r0[tig + 4]);
        qf[kk][3] = __float_as_uint(r0[8 * APi + tig + 4]);
    }

    float o[8][4];
    #pragma unroll
    for (int d = 0; d < 8; ++d)
        #pragma unroll
        for (int t = 0; t < 4; ++t) o[d][t] = 0.f;
    float m0 = -1e30f, m1 = -1e30f, l0 = 0.f, l1 = 0.f;

    const int NT = Nn / AKT;     // 32
    for (int it = 0; it < NT; ++it) {
        const int st = it & 1;
        CP_WAIT1();
        __syncthreads();

        float* kt_ = Ks + st * AKT * APi;
        float* vt_ = Vs + st * AKT * APi;

        // in-place cvt K,V tile to tf32 (cooperative)
        #pragma unroll
        for (int t = 0; t < 4; ++t) {
            int idx = tid + t * 256;
            int r = idx >> 4, c = idx & 15;
            float4* pk = (float4*)(kt_ + r * APi + c * 4);
            float4 v = *pk;
            v.x = f2tf32f(v.x); v.y = f2tf32f(v.y);
            v.z = f2tf32f(v.z); v.w = f2tf32f(v.w);
            *pk = v;
            float4* pv = (float4*)(vt_ + r * APi + c * 4);
            v = *pv;
            v.x = f2tf32f(v.x); v.y = f2tf32f(v.y);
            v.z = f2tf32f(v.z); v.w = f2tf32f(v.w);
            *pv = v;
        }
        __syncthreads();

        // ---- S = Q K^T ----
        float s[8][4];
        #pragma unroll
        for (int nf = 0; nf < 8; ++nf) {
            s[nf][0] = 0.f; s[nf][1] = 0.f; s[nf][2] = 0.f; s[nf][3] = 0.f;
            const float* kr = kt_ + (8 * nf + g) * APi;
            #pragma unroll
            for (int kk = 0; kk < 8; ++kk) {
                uint32_t bf[2];
                bf[0] = __float_as_uint(kr[8 * kk + tig]);
                bf[1] = __float_as_uint(kr[8 * kk + tig + 4]);
                mma_tf32(s[nf], qf[kk], bf);
            }
        }

        // ---- softmax update ----
        float t0 = -1e30f, t1 = -1e30f;
        #pragma unroll
        for (int nf = 0; nf < 8; ++nf) {
            t0 = fmaxf(t0, fmaxf(s[nf][0], s[nf][1]));
            t1 = fmaxf(t1, fmaxf(s[nf][2], s[nf][3]));
        }
        t0 = fmaxf(t0, __shfl_xor_sync(0xffffffff, t0, 1));
        t0 = fmaxf(t0, __shfl_xor_sync(0xffffffff, t0, 2));
        t1 = fmaxf(t1, __shfl_xor_sync(0xffffffff, t1, 1));
        t1 = fmaxf(t1, __shfl_xor_sync(0xffffffff, t1, 2));
        const float nm0 = fmaxf(m0, t0), nm1 = fmaxf(m1, t1);
        const float c0 = __expf(m0 - nm0), c1 = __expf(m1 - nm1);
        m0 = nm0; m1 = nm1;
        l0 *= c0; l1 *= c1;
        #pragma unroll
        for (int d = 0; d < 8; ++d) {
            o[d][0] *= c0; o[d][1] *= c0;
            o[d][2] *= c1; o[d][3] *= c1;
        }

        // ---- P = exp(S-m), permute C-layout -> A-layout ----
        uint32_t pa[8][4];
        const int src1 = (lid & ~3) | (tig >> 1);
        const int src2 = src1 + 2;
        #pragma unroll
        for (int nf = 0; nf < 8; ++nf) {
            float p0 = __expf(s[nf][0] - m0);
            float p1 = __expf(s[nf][1] - m0);
            float p2 = __expf(s[nf][2] - m1);
            float p3 = __expf(s[nf][3] - m1);
            l0 += p0 + p1;
            l1 += p2 + p3;
            uint32_t u0 = f2tf32(p0), u1 = f2tf32(p1);
            uint32_t u2 = f2tf32(p2), u3 = f2tf32(p3);
            uint32_t a00 = __shfl_sync(0xffffffff, u0, src1);
            uint32_t a01 = __shfl_sync(0xffffffff, u1, src1);
            uint32_t a10 = __shfl_sync(0xffffffff, u0, src2);
            uint32_t a11 = __shfl_sync(0xffffffff, u1, src2);
            pa[nf][0] = (tig & 1) ? a01 : a00;
            pa[nf][2] = (tig & 1) ? a11 : a10;
            a00 = __shfl_sync(0xffffffff, u2, src1);
            a01 = __shfl_sync(0xffffffff, u3, src1);
            a10 = __shfl_sync(0xffffffff, u2, src2);
            a11 = __shfl_sync(0xffffffff, u3, src2);
            pa[nf][1] = (tig & 1) ? a01 : a00;
            pa[nf][3] = (tig & 1) ? a11 : a10;
        }

        // ---- O += P V ----
        #pragma unroll
        for (int kt2 = 0; kt2 < 8; ++kt2) {
            const float* vr0 = vt_ + (8 * kt2 + tig) * APi + g;
            const float* vr1 = vt_ + (8 * kt2 + tig + 4) * APi + g;
            #pragma unroll
            for (int df = 0; df < 8; ++df) {
                uint32_t bf[2];
                bf[0] = __float_as_uint(vr0[8 * df]);
                bf[1] = __float_as_uint(vr1[8 * df]);
                mma_tf32(o[df], pa[kt2], bf);
            }
        }

        __syncthreads();
        if (it + 2 < NT) load_tile(it + 2, st);
        else             CP_COMMIT();
    }

    // ---- finalize ----
    l0 += __shfl_xor_sync(0xffffffff, l0, 1);
    l0 += __shfl_xor_sync(0xffffffff, l0, 2);
    l1 += __shfl_xor_sync(0xffffffff, l1, 1);
    l1 += __shfl_xor_sync(0xffffffff, l1, 2);
    const float inv0 = 1.f / l0, inv1 = 1.f / l1;
    const int qr0 = q0 + wq + g;
    const int qr1 = qr0 + 8;
    #pragma unroll
    for (int df = 0; df < 8; ++df) {
        float2 v0; v0.x = o[df][0] * inv0; v0.y = o[df][1] * inv0;
        float2 v1; v1.x = o[df][2] * inv1; v1.y = o[df][3] * inv1;
        *(float2*)(ctx + (tok0 + qr0) * Cc_ + hoff + 8 * df + 2 * tig) = v0;
        *(float2*)(ctx + (tok0 + qr1) * Cc_ + hoff + 8 * df + 2 * tig) = v1;
    }
}

// ---------------------------------------------------------------------------
// out[row] = res[row] + LayerNorm(x[row]) * w + b     (row length 1024)
// ---------------------------------------------------------------------------
__global__ __launch_bounds__(256)
void ln_residual(const float* __restrict__ x, const float* __restrict__ res,
                 const float* __restrict__ w, const float* __restrict__ bp,
                 float* __restrict__ out)
{
    __shared__ float red[256];
    const int row = blockIdx.x;
    const int tid = threadIdx.x;
    const size_t base = (size_t)row * Cc_;

    float4 v = *(const float4*)(x + base + tid * 4);
    float s = v.x + v.y + v.z + v.w;
    red[tid] = s;
    __syncthreads();
    #pragma unroll
    for (int off = 128; off > 0; off >>= 1) {
        if (tid < off) red[tid] += red[tid + off];
        __syncthreads();
    }
    const float mu = red[0] * (1.0f / Cc_);
    __syncthreads();

    float d0 = v.x - mu, d1 = v.y - mu, d2 = v.z - mu, d3 = v.w - mu;
    red[tid] = d0*d0 + d1*d1 + d2*d2 + d3*d3;
    __syncthreads();
    #pragma unroll
    for (int off = 128; off > 0; off >>= 1) {
        if (tid < off) red[tid] += red[tid + off];
        __syncthreads();
    }
    const float var  = red[0] * (1.0f / Cc_);
    const float rstd = rsqrtf(var + 1e-5f);

    float4 rv = *(const float4*)(res + base + tid * 4);
    float4 wv = *(const float4*)(w + tid * 4);
    float4 bv = *(const float4*)(bp + tid * 4);
    float4 ov;
    ov.x = rv.x + d0 * rstd * wv.x + bv.x;
    ov.y = rv.y + d1 * rstd * wv.y + bv.y;
    ov.z = rv.z + d2 * rstd * wv.z + bv.z;
    ov.w = rv.w + d3 * rstd * wv.w + bv.w;
    *(float4*)(out + base + tid * 4) = ov;
}

// ---------------------------------------------------------------------------
// Launch
// ---------------------------------------------------------------------------
extern "C" void kernel_launch(void* const* d_in, const int* in_sizes, int n_in,
                              void* d_out, int out_size)
{
    const float* x      = (const float*)d_in[0];
    const float* qkv_w  = (const float*)d_in[1];
    const float* proj_w = (const float*)d_in[2];
    const float* proj_b = (const float*)d_in[3];
    const float* ln1_w  = (const float*)d_in[4];
    const float* ln1_b  = (const float*)d_in[5];
    const float* fc1_w  = (const float*)d_in[6];
    const float* fc1_b  = (const float*)d_in[7];
    const float* fc2_w  = (const float*)d_in[8];
    const float* fc2_b  = (const float*)d_in[9];
    const float* ln2_w  = (const float*)d_in[10];
    const float* ln2_b  = (const float*)d_in[11];
    float* out = (float*)d_out;

    float *qkv, *ctx, *res, *hbuf, *mlp;
    cudaGetSymbolAddress((void**)&qkv,  g_qkv);
    cudaGetSymbolAddress((void**)&ctx,  g_ctx);
    cudaGetSymbolAddress((void**)&res,  g_res);
    cudaGetSymbolAddress((void**)&hbuf, g_h);
    cudaGetSymbolAddress((void**)&mlp,  g_mlp);

    cudaFuncSetAttribute(tf32_gemm<0>,
        cudaFuncAttributeMaxDynamicSharedMemorySize, GEMM_SMEM);
    cudaFuncSetAttribute(tf32_gemm<1>,
        cudaFuncAttributeMaxDynamicSharedMemorySize, GEMM_SMEM);
    cudaFuncSetAttribute(attn_mma,
        cudaFuncAttributeMaxDynamicSharedMemorySize, ATT_SMEM);

    // 1) qkv = x @ qkv_w^T            [4096, 3072]
    tf32_gemm<0><<<dim3(3 * Cc_ / GBN, MTOK / GBM), 256, GEMM_SMEM>>>(
        x, qkv_w, nullptr, qkv, MTOK, 3 * Cc_, Cc_);
    // 2) attention -> ctx             [4096, 1024]
    attn_mma<<<dim3(Nn / AQ, Hh, Bb), 256, ATT_SMEM>>>(qkv, ctx);
    // 3) res = ctx @ proj_w^T + proj_b
    tf32_gemm<0><<<dim3(Cc_ / GBN, MTOK / GBM), 256, GEMM_SMEM>>>(
        ctx, proj_w, proj_b, res, MTOK, Cc_, Cc_);
    // 4) res = res + LN(res)  (in place)
    ln_residual<<<MTOK, 256>>>(res, res, ln1_w, ln1_b, res);
    // 5) h = gelu(res @ fc1_w^T + fc1_b)   [4096, 4096]
    tf32_gemm<1><<<dim3(HID / GBN, MTOK / GBM), 256, GEMM_SMEM>>>(
        res, fc1_w, fc1_b, hbuf, MTOK, HID, Cc_);
    // 6) mlp = h @ fc2_w^T + fc2_b
    tf32_gemm<0><<<dim3(Cc_ / GBN, MTOK / GBM), 256, GEMM_SMEM>>>(
        hbuf, fc2_w, fc2_b, mlp, MTOK, Cc_, HID);
    // 7) out = res + LN(mlp)
    ln_residual<<<MTOK, 256>>>(mlp, res, ln2_w, ln2_b, out);
}

// round 6
// speedup vs baseline: 3.4334x; 1.0958x over previous
#include <cuda_runtime.h>
#include <math.h>
#include <stdint.h>

// Problem constants
constexpr int Bb   = 2;
constexpr int Nn   = 2048;
constexpr int Cc_  = 1024;
constexpr int Hh   = 16;
constexpr int HD   = 64;
constexpr int HID  = 4096;
constexpr int MTOK = Bb * Nn;            // 4096 token rows
constexpr float SCALE = 0.125f;          // 64^-0.5

// Scratch (static device allocations; no cudaMalloc allowed)
__device__ float g_qkv [(size_t)MTOK * 3 * Cc_];   // 48 MB (rounded)
__device__ float g_ctx [(size_t)MTOK * Cc_];       // 16 MB (rounded)
__device__ float g_res [(size_t)MTOK * Cc_];       // 16 MB fp32 residual
__device__ float g_resr[(size_t)MTOK * Cc_];       // 16 MB rounded copy
__device__ float g_h   [(size_t)MTOK * HID];       // 64 MB (rounded)
__device__ float g_mlp [(size_t)MTOK * Cc_];       // 16 MB fp32
__device__ float g_xr  [(size_t)MTOK * Cc_];       // 16 MB rounded x
__device__ float g_w1  [(size_t)3 * Cc_ * Cc_];    // 12 MB qkv_w rounded
__device__ float g_w2  [(size_t)Cc_ * Cc_];        //  4 MB proj_w rounded
__device__ float g_w3  [(size_t)HID * Cc_];        // 16 MB fc1_w rounded
__device__ float g_w4  [(size_t)Cc_ * HID];        // 16 MB fc2_w rounded

// ===========================================================================
// helpers
// ===========================================================================
__device__ __forceinline__ uint32_t smem_u32(const void* p) {
    uint32_t a;
    asm("{ .reg .u64 t; cvta.to.shared.u64 t, %1; cvt.u32.u64 %0, t; }"
        : "=r"(a) : "l"(p));
    return a;
}
__device__ __forceinline__ void cp_async16(uint32_t dst, const void* src) {
    asm volatile("cp.async.cg.shared.global [%0], [%1], 16;"
                 :: "r"(dst), "l"(src));
}
#define CP_COMMIT() asm volatile("cp.async.commit_group;" ::: "memory")
#define CP_WAIT1()  asm volatile("cp.async.wait_group 1;" ::: "memory")
#define CP_WAIT2()  asm volatile("cp.async.wait_group 2;" ::: "memory")

__device__ __forceinline__ uint32_t f2tf32(float f) {
    uint32_t u;
    asm("cvt.rna.tf32.f32 %0, %1;" : "=r"(u) : "f"(f));
    return u;
}
__device__ __forceinline__ float f2tf32f(float f) {
    return __uint_as_float(f2tf32(f));
}

// mma.sync m16n8k8 tf32, fp32 accumulate
__device__ __forceinline__ void mma_tf32(float* c, const uint32_t* a,
                                         const uint32_t* b) {
    asm volatile(
        "mma.sync.aligned.m16n8k8.row.col.f32.tf32.tf32.f32 "
        "{%0,%1,%2,%3}, {%4,%5,%6,%7}, {%8,%9}, {%0,%1,%2,%3};"
        : "+f"(c[0]), "+f"(c[1]), "+f"(c[2]), "+f"(c[3])
        : "r"(a[0]), "r"(a[1]), "r"(a[2]), "r"(a[3]),
          "r"(b[0]), "r"(b[1]));
}

__device__ __forceinline__ float gelu_exact(float v) {
    return 0.5f * v * (1.0f + erff(v * 0.70710678118654752f));
}

// ---------------------------------------------------------------------------
// Elementwise tf32 rounding pass (producer-side): out[i] = tf32(in[i])
// ---------------------------------------------------------------------------
__global__ __launch_bounds__(256)
void round_tf32(const float* __restrict__ in, float* __restrict__ out, int n4)
{
    int i = blockIdx.x * 256 + threadIdx.x;
    if (i >= n4) return;
    float4 v = ((const float4*)in)[i];
    v.x = f2tf32f(v.x); v.y = f2tf32f(v.y);
    v.z = f2tf32f(v.z); v.w = f2tf32f(v.w);
    ((float4*)out)[i] = v;
}

// ===========================================================================
// tf32 mma.sync GEMM (NT): C[M,N] = A[M,K] @ B[N,K]^T (+bias)(+gelu)(+round)
// A and B must be PRE-ROUNDED to tf32 values. No cvt in the hot loop.
// ===========================================================================
constexpr int GBM = 128, GBN = 128, GBK = 32;
constexpr int GPITCH = GBK + 4;                     // 36 floats
constexpr int STAGE_F = GBM * GPITCH;
constexpr int GEMM_SMEM = 2 * 2 * STAGE_F * 4;      // 73728 B

template<int EPI, int RND>   // EPI: 0 bias, 1 bias+gelu. RND: round output
__global__ __launch_bounds__(256, 2)
void tf32_gemm(const float* __restrict__ A, const float* __restrict__ Bw,
               const float* __restrict__ bias, float* __restrict__ Co,
               int M, int N, int K)
{
    extern __shared__ float smem[];
    float* As = smem;
    float* Bs = smem + 2 * STAGE_F;
    const uint32_t As_u = smem_u32(As);
    const uint32_t Bs_u = smem_u32(Bs);

    const int tid = threadIdx.x;
    const int wid = tid >> 5;
    const int lid = tid & 31;
    const int g   = lid >> 2;
    const int tig = lid & 3;
    const int wm  = (wid & 1) * 64;
    const int wn  = (wid >> 1) * 32;
    const int m0  = blockIdx.y * GBM;
    const int n0  = blockIdx.x * GBN;
    const int NC  = K / GBK;

    float acc[4][4][4];
    #pragma unroll
    for (int i = 0; i < 4; ++i)
        #pragma unroll
        for (int j = 0; j < 4; ++j)
            #pragma unroll
            for (int t = 0; t < 4; ++t) acc[i][j][t] = 0.f;

    auto load_chunk = [&](int kc, int st) {
        const int k0f = kc * GBK;
        const uint32_t abase = As_u + st * STAGE_F * 4;
        const uint32_t bbase = Bs_u + st * STAGE_F * 4;
        #pragma unroll
        for (int t = 0; t < 4; ++t) {
            int idx = tid + t * 256;
            int r   = idx >> 3;
            int c   = idx & 7;
            uint32_t off = (uint32_t)(r * (GPITCH * 4) + c * 16);
            cp_async16(abase + off, A + (size_t)(m0 + r) * K + k0f + c * 4);
            cp_async16(bbase + off, Bw + (size_t)(n0 + r) * K + k0f + c * 4);
        }
        CP_COMMIT();
    };

    load_chunk(0, 0);
    load_chunk(1, 1);

    for (int i = 0; i < NC; ++i) {
        const int st = i & 1;
        CP_WAIT1();
        __syncthreads();

        const uint32_t* Ast = (const uint32_t*)(As + st * STAGE_F);
        const uint32_t* Bst = (const uint32_t*)(Bs + st * STAGE_F);

        #pragma unroll
        for (int kk = 0; kk < 4; ++kk) {
            const int kc = kk * 8;
            uint32_t af[4][4], bf[4][2];
            #pragma unroll
            for (int mf = 0; mf < 4; ++mf) {
                const uint32_t* r0 = Ast + (wm + mf * 16 + g) * GPITCH + kc;
                const uint32_t* r1 = r0 + 8 * GPITCH;
                af[mf][0] = r0[tig];
                af[mf][1] = r1[tig];
                af[mf][2] = r0[tig + 4];
                af[mf][3] = r1[tig + 4];
            }
            #pragma unroll
            for (int nf = 0; nf < 4; ++nf) {
                const uint32_t* rb = Bst + (wn + nf * 8 + g) * GPITCH + kc;
                bf[nf][0] = rb[tig];
                bf[nf][1] = rb[tig + 4];
            }
            #pragma unroll
            for (int mf = 0; mf < 4; ++mf)
                #pragma unroll
                for (int nf = 0; nf < 4; ++nf)
                    mma_tf32(acc[mf][nf], af[mf], bf[nf]);
        }

        __syncthreads();
        if (i + 2 < NC) load_chunk(i + 2, st);
        else            CP_COMMIT();
    }

    #pragma unroll
    for (int mf = 0; mf < 4; ++mf) {
        const int r0 = m0 + wm + mf * 16 + g;
        const int r1 = r0 + 8;
        #pragma unroll
        for (int nf = 0; nf < 4; ++nf) {
            const int col = n0 + wn + nf * 8 + tig * 2;
            float b0 = 0.f, b1 = 0.f;
            if (bias) { b0 = bias[col]; b1 = bias[col + 1]; }
            float t0 = acc[mf][nf][0] + b0;
            float t1 = acc[mf][nf][1] + b1;
            float t2 = acc[mf][nf][2] + b0;
            float t3 = acc[mf][nf][3] + b1;
            if (EPI == 1) {
                t0 = gelu_exact(t0); t1 = gelu_exact(t1);
                t2 = gelu_exact(t2); t3 = gelu_exact(t3);
            }
            if (RND == 1) {
                t0 = f2tf32f(t0); t1 = f2tf32f(t1);
                t2 = f2tf32f(t2); t3 = f2tf32f(t3);
            }
            float2 v0; v0.x = t0; v0.y = t1;
            float2 v1; v1.x = t2; v1.y = t3;
            *(float2*)(Co + (size_t)r0 * N + col) = v0;
            *(float2*)(Co + (size_t)r1 * N + col) = v1;
        }
    }
}

// ===========================================================================
// Flash attention via mma.sync tf32. qkv buffer is PRE-ROUNDED.
// SCALE applied to S post-MMA. ctx output written tf32-rounded.
// ===========================================================================
constexpr int AQ  = 128;
constexpr int AKT = 64;
constexpr int APi = 68;
constexpr int A_KS = AQ * APi;
constexpr int A_VS = A_KS + 2 * AKT * APi;
constexpr int ATT_SMEM = (A_VS + 2 * AKT * APi) * 4;   // 104448 B

__global__ __launch_bounds__(256, 1)
void attn_mma(const float* __restrict__ qkv, float* __restrict__ ctx)
{
    extern __shared__ float sm[];
    float* Qs = sm;
    float* Ks = sm + A_KS;
    float* Vs = sm + A_VS;
    const uint32_t Qs_u = smem_u32(Qs);
    const uint32_t Ks_u = smem_u32(Ks);
    const uint32_t Vs_u = smem_u32(Vs);

    const int tid = threadIdx.x;
    const int wid = tid >> 5;
    const int lid = tid & 31;
    const int g   = lid >> 2;
    const int tig = lid & 3;
    const int q0  = blockIdx.x * AQ;
    const int h   = blockIdx.y;
    const int b   = blockIdx.z;
    const int wq  = wid * 16;

    const size_t tok0 = (size_t)(b * Nn);
    const int hoff = h * HD;

    // group 0: Q tile (128 x 64)
    #pragma unroll
    for (int t = 0; t < 8; ++t) {
        int idx = tid + t * 256;
        int r = idx >> 4, c = idx & 15;
        cp_async16(Qs_u + (uint32_t)(r * APi + c * 4) * 4,
                   qkv + (tok0 + q0 + r) * (3 * Cc_) + hoff + c * 4);
    }
    CP_COMMIT();

    auto load_tile = [&](int kt, int st) {
        const int k0 = kt * AKT;
        const uint32_t kb = Ks_u + (uint32_t)(st * AKT * APi) * 4;
        const uint32_t vb = Vs_u + (uint32_t)(st * AKT * APi) * 4;
        #pragma unroll
        for (int t = 0; t < 4; ++t) {
            int idx = tid + t * 256;
            int r = idx >> 4, c = idx & 15;
            const float* src = qkv + (tok0 + k0 + r) * (3 * Cc_) + Cc_ + hoff + c * 4;
            uint32_t off = (uint32_t)(r * APi + c * 4) * 4;
            cp_async16(kb + off, src);
            cp_async16(vb + off, src + Cc_);
        }
        CP_COMMIT();
    };
    load_tile(0, 0);
    load_tile(1, 1);

    CP_WAIT2();
    __syncthreads();

    // Q fragments (values already tf32-rounded)
    uint32_t qf[8][4];
    #pragma unroll
    for (int kk = 0; kk < 8; ++kk) {
        const uint32_t* r0 = (const uint32_t*)(Qs + (wq + g) * APi + kk * 8);
        qf[kk][0] = r0[tig];
        qf[kk][1] = r0[8 * APi + tig];
        qf[kk][2] = r0[tig + 4];
        qf[kk][3] = r0[8 * APi + tig + 4];
    }

    float o[8][4];
    #pragma unroll
    for (int d = 0; d < 8; ++d)
        #pragma unroll
        for (int t = 0; t < 4; ++t) o[d][t] = 0.f;
    float m0 = -1e30f, m1 = -1e30f, l0 = 0.f, l1 = 0.f;

    const int NT = Nn / AKT;     // 32
    for (int it = 0; it < NT; ++it) {
        const int st = it & 1;
        CP_WAIT1();
        __syncthreads();

        const float* kt_ = Ks + st * AKT * APi;
        const float* vt_ = Vs + st * AKT * APi;

        // ---- S = Q K^T  (then * SCALE) ----
        float s[8][4];
        #pragma unroll
        for (int nf = 0; nf < 8; ++nf) {
            s[nf][0] = 0.f; s[nf][1] = 0.f; s[nf][2] = 0.f; s[nf][3] = 0.f;
            const uint32_t* kr = (const uint32_t*)(kt_ + (8 * nf + g) * APi);
            #pragma unroll
            for (int kk = 0; kk < 8; ++kk) {
                uint32_t bf[2];
                bf[0] = kr[8 * kk + tig];
                bf[1] = kr[8 * kk + tig + 4];
                mma_tf32(s[nf], qf[kk], bf);
            }
            s[nf][0] *= SCALE; s[nf][1] *= SCALE;
            s[nf][2] *= SCALE; s[nf][3] *= SCALE;
        }

        // ---- softmax update ----
        float t0 = -1e30f, t1 = -1e30f;
        #pragma unroll
        for (int nf = 0; nf < 8; ++nf) {
            t0 = fmaxf(t0, fmaxf(s[nf][0], s[nf][1]));
            t1 = fmaxf(t1, fmaxf(s[nf][2], s[nf][3]));
        }
        t0 = fmaxf(t0, __shfl_xor_sync(0xffffffff, t0, 1));
        t0 = fmaxf(t0, __shfl_xor_sync(0xffffffff, t0, 2));
        t1 = fmaxf(t1, __shfl_xor_sync(0xffffffff, t1, 1));
        t1 = fmaxf(t1, __shfl_xor_sync(0xffffffff, t1, 2));
        const float nm0 = fmaxf(m0, t0), nm1 = fmaxf(m1, t1);
        const float c0 = __expf(m0 - nm0), c1 = __expf(m1 - nm1);
        m0 = nm0; m1 = nm1;
        l0 *= c0; l1 *= c1;
        #pragma unroll
        for (int d = 0; d < 8; ++d) {
            o[d][0] *= c0; o[d][1] *= c0;
            o[d][2] *= c1; o[d][3] *= c1;
        }

        // ---- P = exp(S-m), permute C-layout -> A-layout ----
        uint32_t pa[8][4];
        const int src1 = (lid & ~3) | (tig >> 1);
        const int src2 = src1 + 2;
        #pragma unroll
        for (int nf = 0; nf < 8; ++nf) {
            float p0 = __expf(s[nf][0] - m0);
            float p1 = __expf(s[nf][1] - m0);
            float p2 = __expf(s[nf][2] - m1);
            float p3 = __expf(s[nf][3] - m1);
            l0 += p0 + p1;
            l1 += p2 + p3;
            uint32_t u0 = f2tf32(p0), u1 = f2tf32(p1);
            uint32_t u2 = f2tf32(p2), u3 = f2tf32(p3);
            uint32_t a00 = __shfl_sync(0xffffffff, u0, src1);
            uint32_t a01 = __shfl_sync(0xffffffff, u1, src1);
            uint32_t a10 = __shfl_sync(0xffffffff, u0, src2);
            uint32_t a11 = __shfl_sync(0xffffffff, u1, src2);
            pa[nf][0] = (tig & 1) ? a01 : a00;
            pa[nf][2] = (tig & 1) ? a11 : a10;
            a00 = __shfl_sync(0xffffffff, u2, src1);
            a01 = __shfl_sync(0xffffffff, u3, src1);
            a10 = __shfl_sync(0xffffffff, u2, src2);
            a11 = __shfl_sync(0xffffffff, u3, src2);
            pa[nf][1] = (tig & 1) ? a01 : a00;
            pa[nf][3] = (tig & 1) ? a11 : a10;
        }

        // ---- O += P V ----
        #pragma unroll
        for (int kt2 = 0; kt2 < 8; ++kt2) {
            const uint32_t* vr0 = (const uint32_t*)(vt_ + (8 * kt2 + tig) * APi + g);
            const uint32_t* vr1 = (const uint32_t*)(vt_ + (8 * kt2 + tig + 4) * APi + g);
            #pragma unroll
            for (int df = 0; df < 8; ++df) {
                uint32_t bf[2];
                bf[0] = vr0[8 * df];
                bf[1] = vr1[8 * df];
                mma_tf32(o[df], pa[kt2], bf);
            }
        }

        __syncthreads();
        if (it + 2 < NT) load_tile(it + 2, st);
        else             CP_COMMIT();
    }

    // ---- finalize (round for proj GEMM consumption) ----
    l0 += __shfl_xor_sync(0xffffffff, l0, 1);
    l0 += __shfl_xor_sync(0xffffffff, l0, 2);
    l1 += __shfl_xor_sync(0xffffffff, l1, 1);
    l1 += __shfl_xor_sync(0xffffffff, l1, 2);
    const float inv0 = 1.f / l0, inv1 = 1.f / l1;
    const int qr0 = q0 + wq + g;
    const int qr1 = qr0 + 8;
    #pragma unroll
    for (int df = 0; df < 8; ++df) {
        float2 v0, v1;
        v0.x = f2tf32f(o[df][0] * inv0); v0.y = f2tf32f(o[df][1] * inv0);
        v1.x = f2tf32f(o[df][2] * inv1); v1.y = f2tf32f(o[df][3] * inv1);
        *(float2*)(ctx + (tok0 + qr0) * Cc_ + hoff + 8 * df + 2 * tig) = v0;
        *(float2*)(ctx + (tok0 + qr1) * Cc_ + hoff + 8 * df + 2 * tig) = v1;
    }
}

// ---------------------------------------------------------------------------
// out[row] = res[row] + LayerNorm(x[row]) * w + b     (row length 1024)
// DUAL=1: also write tf32-rounded copy to out_r (for GEMM consumption).
// ---------------------------------------------------------------------------
template<int DUAL>
__global__ __launch_bounds__(256)
void ln_residual(const float* __restrict__ x, const float* __restrict__ res,
                 const float* __restrict__ w, const float* __restrict__ bp,
                 float* __restrict__ out, float* __restrict__ out_r)
{
    __shared__ float red[256];
    const int row = blockIdx.x;
    const int tid = threadIdx.x;
    const size_t base = (size_t)row * Cc_;

    float4 v = *(const float4*)(x + base + tid * 4);
    float s = v.x + v.y + v.z + v.w;
    red[tid] = s;
    __syncthreads();
    #pragma unroll
    for (int off = 128; off > 0; off >>= 1) {
        if (tid < off) red[tid] += red[tid + off];
        __syncthreads();
    }
    const float mu = red[0] * (1.0f / Cc_);
    __syncthreads();

    float d0 = v.x - mu, d1 = v.y - mu, d2 = v.z - mu, d3 = v.w - mu;
    red[tid] = d0*d0 + d1*d1 + d2*d2 + d3*d3;
    __syncthreads();
    #pragma unroll
    for (int off = 128; off > 0; off >>= 1) {
        if (tid < off) red[tid] += red[tid + off];
        __syncthreads();
    }
    const float var  = red[0] * (1.0f / Cc_);
    const float rstd = rsqrtf(var + 1e-5f);

    float4 rv = *(const float4*)(res + base + tid * 4);
    float4 wv = *(const float4*)(w + tid * 4);
    float4 bv = *(const float4*)(bp + tid * 4);
    float4 ov;
    ov.x = rv.x + d0 * rstd * wv.x + bv.x;
    ov.y = rv.y + d1 * rstd * wv.y + bv.y;
    ov.z = rv.z + d2 * rstd * wv.z + bv.z;
    ov.w = rv.w + d3 * rstd * wv.w + bv.w;
    *(float4*)(out + base + tid * 4) = ov;
    if (DUAL == 1) {
        float4 rr;
        rr.x = f2tf32f(ov.x); rr.y = f2tf32f(ov.y);
        rr.z = f2tf32f(ov.z); rr.w = f2tf32f(ov.w);
        *(float4*)(out_r + base + tid * 4) = rr;
    }
}

// ---------------------------------------------------------------------------
// Launch
// ---------------------------------------------------------------------------
extern "C" void kernel_launch(void* const* d_in, const int* in_sizes, int n_in,
                              void* d_out, int out_size)
{
    const float* x      = (const float*)d_in[0];
    const float* qkv_w  = (const float*)d_in[1];
    const float* proj_w = (const float*)d_in[2];
    const float* proj_b = (const float*)d_in[3];
    const float* ln1_w  = (const float*)d_in[4];
    const float* ln1_b  = (const float*)d_in[5];
    const float* fc1_w  = (const float*)d_in[6];
    const float* fc1_b  = (const float*)d_in[7];
    const float* fc2_w  = (const float*)d_in[8];
    const float* fc2_b  = (const float*)d_in[9];
    const float* ln2_w  = (const float*)d_in[10];
    const float* ln2_b  = (const float*)d_in[11];
    float* out = (float*)d_out;

    float *qkv, *ctx, *res, *resr, *hbuf, *mlp, *xr, *w1, *w2, *w3, *w4;
    cudaGetSymbolAddress((void**)&qkv,  g_qkv);
    cudaGetSymbolAddress((void**)&ctx,  g_ctx);
    cudaGetSymbolAddress((void**)&res,  g_res);
    cudaGetSymbolAddress((void**)&resr, g_resr);
    cudaGetSymbolAddress((void**)&hbuf, g_h);
    cudaGetSymbolAddress((void**)&mlp,  g_mlp);
    cudaGetSymbolAddress((void**)&xr,   g_xr);
    cudaGetSymbolAddress((void**)&w1,   g_w1);
    cudaGetSymbolAddress((void**)&w2,   g_w2);
    cudaGetSymbolAddress((void**)&w3,   g_w3);
    cudaGetSymbolAddress((void**)&w4,   g_w4);

    cudaFuncSetAttribute(tf32_gemm<0,0>,
        cudaFuncAttributeMaxDynamicSharedMemorySize, GEMM_SMEM);
    cudaFuncSetAttribute(tf32_gemm<0,1>,
        cudaFuncAttributeMaxDynamicSharedMemorySize, GEMM_SMEM);
    cudaFuncSetAttribute(tf32_gemm<1,1>,
        cudaFuncAttributeMaxDynamicSharedMemorySize, GEMM_SMEM);
    cudaFuncSetAttribute(attn_mma,
        cudaFuncAttributeMaxDynamicSharedMemorySize, ATT_SMEM);

    // 0) producer-side tf32 rounding of GEMM operands
    auto rlaunch = [](const float* src, float* dst, size_t n) {
        int n4 = (int)(n / 4);
        round_tf32<<<(n4 + 255) / 256, 256>>>(src, dst, n4);
    };
    rlaunch(x,      xr, (size_t)MTOK * Cc_);
    rlaunch(qkv_w,  w1, (size_t)3 * Cc_ * Cc_);
    rlaunch(proj_w, w2, (size_t)Cc_ * Cc_);
    rlaunch(fc1_w,  w3, (size_t)HID * Cc_);
    rlaunch(fc2_w,  w4, (size_t)Cc_ * HID);

    // 1) qkv = x @ qkv_w^T  (output rounded for attention)
    tf32_gemm<0,1><<<dim3(3 * Cc_ / GBN, MTOK / GBM), 256, GEMM_SMEM>>>(
        xr, w1, nullptr, qkv, MTOK, 3 * Cc_, Cc_);
    // 2) attention -> ctx (rounded)
    attn_mma<<<dim3(Nn / AQ, Hh, Bb), 256, ATT_SMEM>>>(qkv, ctx);
    // 3) res = ctx @ proj_w^T + proj_b   (fp32 output — residual base)
    tf32_gemm<0,0><<<dim3(Cc_ / GBN, MTOK / GBM), 256, GEMM_SMEM>>>(
        ctx, w2, proj_b, res, MTOK, Cc_, Cc_);
    // 4) res = res + LN(res); also write rounded copy resr
    ln_residual<1><<<MTOK, 256>>>(res, res, ln1_w, ln1_b, res, resr);
    // 5) h = gelu(resr @ fc1_w^T + fc1_b)  (output rounded for fc2)
    tf32_gemm<1,1><<<dim3(HID / GBN, MTOK / GBM), 256, GEMM_SMEM>>>(
        resr, w3, fc1_b, hbuf, MTOK, HID, Cc_);
    // 6) mlp = h @ fc2_w^T + fc2_b   (fp32 output)
    tf32_gemm<0,0><<<dim3(Cc_ / GBN, MTOK / GBM), 256, GEMM_SMEM>>>(
        hbuf, w4, fc2_b, mlp, MTOK, Cc_, HID);
    // 7) out = res + LN(mlp)
    ln_residual<0><<<MTOK, 256>>>(mlp, res, ln2_w, ln2_b, out, nullptr);
}

// round 7
// speedup vs baseline: 4.9591x; 1.4444x over previous
#include <cuda_runtime.h>
#include <cuda_fp16.h>
#include <math.h>
#include <stdint.h>

// Problem constants
constexpr int Bb   = 2;
constexpr int Nn   = 2048;
constexpr int Cc_  = 1024;
constexpr int Hh   = 16;
constexpr int HD   = 64;
constexpr int HID  = 4096;
constexpr int MTOK = Bb * Nn;            // 4096 token rows
constexpr float SCALE = 0.125f;          // 64^-0.5

// Scratch (static device allocations; no cudaMalloc allowed)
__device__ float  g_qkv [(size_t)MTOK * 3 * Cc_];   // 48 MB (tf32-rounded f32)
__device__ __half g_ctx [(size_t)MTOK * Cc_];       //  8 MB
__device__ float  g_res [(size_t)MTOK * Cc_];       // 16 MB fp32 residual
__device__ __half g_resr[(size_t)MTOK * Cc_];       //  8 MB half copy
__device__ __half g_h   [(size_t)MTOK * HID];       // 32 MB
__device__ float  g_mlp [(size_t)MTOK * Cc_];       // 16 MB fp32
__device__ __half g_xh  [(size_t)MTOK * Cc_];       //  8 MB half x
__device__ __half g_w1  [(size_t)3 * Cc_ * Cc_];    //  6 MB
__device__ __half g_w2  [(size_t)Cc_ * Cc_];        //  2 MB
__device__ __half g_w3  [(size_t)HID * Cc_];        //  8 MB
__device__ __half g_w4  [(size_t)Cc_ * HID];        //  8 MB

// ===========================================================================
// helpers
// ===========================================================================
__device__ __forceinline__ uint32_t smem_u32(const void* p) {
    uint32_t a;
    asm("{ .reg .u64 t; cvta.to.shared.u64 t, %1; cvt.u32.u64 %0, t; }"
        : "=r"(a) : "l"(p));
    return a;
}
__device__ __forceinline__ void cp_async16(uint32_t dst, const void* src) {
    asm volatile("cp.async.cg.shared.global [%0], [%1], 16;"
                 :: "r"(dst), "l"(src));
}
#define CP_COMMIT() asm volatile("cp.async.commit_group;" ::: "memory")
#define CP_WAIT1()  asm volatile("cp.async.wait_group 1;" ::: "memory")
#define CP_WAIT2()  asm volatile("cp.async.wait_group 2;" ::: "memory")

__device__ __forceinline__ uint32_t f2tf32(float f) {
    uint32_t u;
    asm("cvt.rna.tf32.f32 %0, %1;" : "=r"(u) : "f"(f));
    return u;
}
__device__ __forceinline__ float f2tf32f(float f) {
    return __uint_as_float(f2tf32(f));
}

// mma.sync m16n8k8 tf32 (attention)
__device__ __forceinline__ void mma_tf32(float* c, const uint32_t* a,
                                         const uint32_t* b) {
    asm volatile(
        "mma.sync.aligned.m16n8k8.row.col.f32.tf32.tf32.f32 "
        "{%0,%1,%2,%3}, {%4,%5,%6,%7}, {%8,%9}, {%0,%1,%2,%3};"
        : "+f"(c[0]), "+f"(c[1]), "+f"(c[2]), "+f"(c[3])
        : "r"(a[0]), "r"(a[1]), "r"(a[2]), "r"(a[3]),
          "r"(b[0]), "r"(b[1]));
}

// mma.sync m16n8k16 f16 (GEMMs)
__device__ __forceinline__ void mma_f16(float* c, const uint32_t* a,
                                        const uint32_t* b) {
    asm volatile(
        "mma.sync.aligned.m16n8k16.row.col.f32.f16.f16.f32 "
        "{%0,%1,%2,%3}, {%4,%5,%6,%7}, {%8,%9}, {%0,%1,%2,%3};"
        : "+f"(c[0]), "+f"(c[1]), "+f"(c[2]), "+f"(c[3])
        : "r"(a[0]), "r"(a[1]), "r"(a[2]), "r"(a[3]),
          "r"(b[0]), "r"(b[1]));
}

__device__ __forceinline__ float gelu_exact(float v) {
    return 0.5f * v * (1.0f + erff(v * 0.70710678118654752f));
}

// ---------------------------------------------------------------------------
// Elementwise fp16 conversion pass: out[i] = half(in[i])
// ---------------------------------------------------------------------------
__global__ __launch_bounds__(256)
void to_half(const float* __restrict__ in, __half* __restrict__ out, int n4)
{
    int i = blockIdx.x * 256 + threadIdx.x;
    if (i >= n4) return;
    float4 v = ((const float4*)in)[i];
    __half2* o2 = (__half2*)out;
    o2[2 * i + 0] = __floats2half2_rn(v.x, v.y);
    o2[2 * i + 1] = __floats2half2_rn(v.z, v.w);
}

// ===========================================================================
// fp16 mma.sync GEMM (NT): C[M,N] = A[M,K] @ B[N,K]^T (+bias)(+gelu)
// A,B row-major __half (K contiguous). BM=BN=128, BK=64 halves, 256 threads,
// 8 warps (2x4), warp tile 64x32, smem pitch 72 halves (conflict-free).
// OUT: 0 = f32, 1 = f32 tf32-rounded, 2 = f16.
// ===========================================================================
constexpr int GBM = 128, GBN = 128, HBK = 64;
constexpr int HPITCH = HBK + 8;                     // 72 halves = 144 B
constexpr int STAGE_H = GBM * HPITCH;               // halves per operand stage
constexpr int GEMM_SMEM = 2 * 2 * STAGE_H * 2;      // 73728 B

template<int EPI, int OUT>
__global__ __launch_bounds__(256, 2)
void h_gemm(const __half* __restrict__ A, const __half* __restrict__ Bw,
            const float* __restrict__ bias, void* __restrict__ Co,
            int M, int N, int K)
{
    extern __shared__ __half smemh[];
    __half* As = smemh;
    __half* Bs = smemh + 2 * STAGE_H;
    const uint32_t As_u = smem_u32(As);
    const uint32_t Bs_u = smem_u32(Bs);

    const int tid = threadIdx.x;
    const int wid = tid >> 5;
    const int lid = tid & 31;
    const int g   = lid >> 2;
    const int tig = lid & 3;
    const int wm  = (wid & 1) * 64;
    const int wn  = (wid >> 1) * 32;
    const int m0  = blockIdx.y * GBM;
    const int n0  = blockIdx.x * GBN;
    const int NC  = K / HBK;

    float acc[4][4][4];
    #pragma unroll
    for (int i = 0; i < 4; ++i)
        #pragma unroll
        for (int j = 0; j < 4; ++j)
            #pragma unroll
            for (int t = 0; t < 4; ++t) acc[i][j][t] = 0.f;

    // tile = 128 rows x 8 chunks(16B = 8 halves) = 1024 chunks; 4/thread
    auto load_chunk = [&](int kc, int st) {
        const int k0h = kc * HBK;
        const uint32_t abase = As_u + st * STAGE_H * 2;
        const uint32_t bbase = Bs_u + st * STAGE_H * 2;
        #pragma unroll
        for (int t = 0; t < 4; ++t) {
            int idx = tid + t * 256;
            int r   = idx >> 3;
            int c   = idx & 7;
            uint32_t off = (uint32_t)(r * (HPITCH * 2) + c * 16);
            cp_async16(abase + off, A + (size_t)(m0 + r) * K + k0h + c * 8);
            cp_async16(bbase + off, Bw + (size_t)(n0 + r) * K + k0h + c * 8);
        }
        CP_COMMIT();
    };

    load_chunk(0, 0);
    load_chunk(1, 1);

    for (int i = 0; i < NC; ++i) {
        const int st = i & 1;
        CP_WAIT1();
        __syncthreads();

        const uint32_t* Au = (const uint32_t*)(As + st * STAGE_H);
        const uint32_t* Bu = (const uint32_t*)(Bs + st * STAGE_H);

        #pragma unroll
        for (int kk = 0; kk < 4; ++kk) {           // 4 x K=16
            const int kb = kk * 8;                 // u32 offset
            uint32_t af[4][4], bf[4][2];
            #pragma unroll
            for (int mf = 0; mf < 4; ++mf) {
                const int r0 = (wm + mf * 16 + g) * 36;
                const int r1 = r0 + 8 * 36;
                af[mf][0] = Au[r0 + kb + tig];
                af[mf][1] = Au[r1 + kb + tig];
                af[mf][2] = Au[r0 + kb + tig + 4];
                af[mf][3] = Au[r1 + kb + tig + 4];
            }
            #pragma unroll
            for (int nf = 0; nf < 4; ++nf) {
                const int rb = (wn + nf * 8 + g) * 36;
                bf[nf][0] = Bu[rb + kb + tig];
                bf[nf][1] = Bu[rb + kb + tig + 4];
            }
            #pragma unroll
            for (int mf = 0; mf < 4; ++mf)
                #pragma unroll
                for (int nf = 0; nf < 4; ++nf)
                    mma_f16(acc[mf][nf], af[mf], bf[nf]);
        }

        __syncthreads();
        if (i + 2 < NC) load_chunk(i + 2, st);
        else            CP_COMMIT();
    }

    #pragma unroll
    for (int mf = 0; mf < 4; ++mf) {
        const int r0 = m0 + wm + mf * 16 + g;
        const int r1 = r0 + 8;
        #pragma unroll
        for (int nf = 0; nf < 4; ++nf) {
            const int col = n0 + wn + nf * 8 + tig * 2;
            float b0 = 0.f, b1 = 0.f;
            if (bias) { b0 = bias[col]; b1 = bias[col + 1]; }
            float t0 = acc[mf][nf][0] + b0;
            float t1 = acc[mf][nf][1] + b1;
            float t2 = acc[mf][nf][2] + b0;
            float t3 = acc[mf][nf][3] + b1;
            if (EPI == 1) {
                t0 = gelu_exact(t0); t1 = gelu_exact(t1);
                t2 = gelu_exact(t2); t3 = gelu_exact(t3);
            }
            if (OUT == 0 || OUT == 1) {
                if (OUT == 1) {
                    t0 = f2tf32f(t0); t1 = f2tf32f(t1);
                    t2 = f2tf32f(t2); t3 = f2tf32f(t3);
                }
                float* Cf = (float*)Co;
                float2 v0; v0.x = t0; v0.y = t1;
                float2 v1; v1.x = t2; v1.y = t3;
                *(float2*)(Cf + (size_t)r0 * N + col) = v0;
                *(float2*)(Cf + (size_t)r1 * N + col) = v1;
            } else {
                __half* Ch = (__half*)Co;
                *(__half2*)(Ch + (size_t)r0 * N + col) = __floats2half2_rn(t0, t1);
                *(__half2*)(Ch + (size_t)r1 * N + col) = __floats2half2_rn(t2, t3);
            }
        }
    }
}

// ===========================================================================
// Flash attention via mma.sync tf32. qkv is tf32-rounded fp32.
// ctx output written as __half (for proj GEMM).
// ===========================================================================
constexpr int AQ  = 128;
constexpr int AKT = 64;
constexpr int APi = 68;
constexpr int A_KS = AQ * APi;
constexpr int A_VS = A_KS + 2 * AKT * APi;
constexpr int ATT_SMEM = (A_VS + 2 * AKT * APi) * 4;   // 104448 B

__global__ __launch_bounds__(256, 1)
void attn_mma(const float* __restrict__ qkv, __half* __restrict__ ctx)
{
    extern __shared__ float sm[];
    float* Qs = sm;
    float* Ks = sm + A_KS;
    float* Vs = sm + A_VS;
    const uint32_t Qs_u = smem_u32(Qs);
    const uint32_t Ks_u = smem_u32(Ks);
    const uint32_t Vs_u = smem_u32(Vs);

    const int tid = threadIdx.x;
    const int wid = tid >> 5;
    const int lid = tid & 31;
    const int g   = lid >> 2;
    const int tig = lid & 3;
    const int q0  = blockIdx.x * AQ;
    const int h   = blockIdx.y;
    const int b   = blockIdx.z;
    const int wq  = wid * 16;

    const size_t tok0 = (size_t)(b * Nn);
    const int hoff = h * HD;

    #pragma unroll
    for (int t = 0; t < 8; ++t) {
        int idx = tid + t * 256;
        int r = idx >> 4, c = idx & 15;
        cp_async16(Qs_u + (uint32_t)(r * APi + c * 4) * 4,
                   qkv + (tok0 + q0 + r) * (3 * Cc_) + hoff + c * 4);
    }
    CP_COMMIT();

    auto load_tile = [&](int kt, int st) {
        const int k0 = kt * AKT;
        const uint32_t kb = Ks_u + (uint32_t)(st * AKT * APi) * 4;
        const uint32_t vb = Vs_u + (uint32_t)(st * AKT * APi) * 4;
        #pragma unroll
        for (int t = 0; t < 4; ++t) {
            int idx = tid + t * 256;
            int r = idx >> 4, c = idx & 15;
            const float* src = qkv + (tok0 + k0 + r) * (3 * Cc_) + Cc_ + hoff + c * 4;
            uint32_t off = (uint32_t)(r * APi + c * 4) * 4;
            cp_async16(kb + off, src);
            cp_async16(vb + off, src + Cc_);
        }
        CP_COMMIT();
    };
    load_tile(0, 0);
    load_tile(1, 1);

    CP_WAIT2();
    __syncthreads();

    uint32_t qf[8][4];
    #pragma unroll
    for (int kk = 0; kk < 8; ++kk) {
        const uint32_t* r0 = (const uint32_t*)(Qs + (wq + g) * APi + kk * 8);
        qf[kk][0] = r0[tig];
        qf[kk][1] = r0[8 * APi + tig];
        qf[kk][2] = r0[tig + 4];
        qf[kk][3] = r0[8 * APi + tig + 4];
    }

    float o[8][4];
    #pragma unroll
    for (int d = 0; d < 8; ++d)
        #pragma unroll
        for (int t = 0; t < 4; ++t) o[d][t] = 0.f;
    float m0 = -1e30f, m1 = -1e30f, l0 = 0.f, l1 = 0.f;

    const int NT = Nn / AKT;     // 32
    for (int it = 0; it < NT; ++it) {
        const int st = it & 1;
        CP_WAIT1();
        __syncthreads();

        const float* kt_ = Ks + st * AKT * APi;
        const float* vt_ = Vs + st * AKT * APi;

        float s[8][4];
        #pragma unroll
        for (int nf = 0; nf < 8; ++nf) {
            s[nf][0] = 0.f; s[nf][1] = 0.f; s[nf][2] = 0.f; s[nf][3] = 0.f;
            const uint32_t* kr = (const uint32_t*)(kt_ + (8 * nf + g) * APi);
            #pragma unroll
            for (int kk = 0; kk < 8; ++kk) {
                uint32_t bf[2];
                bf[0] = kr[8 * kk + tig];
                bf[1] = kr[8 * kk + tig + 4];
                mma_tf32(s[nf], qf[kk], bf);
            }
            s[nf][0] *= SCALE; s[nf][1] *= SCALE;
            s[nf][2] *= SCALE; s[nf][3] *= SCALE;
        }

        float t0 = -1e30f, t1 = -1e30f;
        #pragma unroll
        for (int nf = 0; nf < 8; ++nf) {
            t0 = fmaxf(t0, fmaxf(s[nf][0], s[nf][1]));
            t1 = fmaxf(t1, fmaxf(s[nf][2], s[nf][3]));
        }
        t0 = fmaxf(t0, __shfl_xor_sync(0xffffffff, t0, 1));
        t0 = fmaxf(t0, __shfl_xor_sync(0xffffffff, t0, 2));
        t1 = fmaxf(t1, __shfl_xor_sync(0xffffffff, t1, 1));
        t1 = fmaxf(t1, __shfl_xor_sync(0xffffffff, t1, 2));
        const float nm0 = fmaxf(m0, t0), nm1 = fmaxf(m1, t1);
        const float c0 = __expf(m0 - nm0), c1 = __expf(m1 - nm1);
        m0 = nm0; m1 = nm1;
        l0 *= c0; l1 *= c1;
        #pragma unroll
        for (int d = 0; d < 8; ++d) {
            o[d][0] *= c0; o[d][1] *= c0;
            o[d][2] *= c1; o[d][3] *= c1;
        }

        uint32_t pa[8][4];
        const int src1 = (lid & ~3) | (tig >> 1);
        const int src2 = src1 + 2;
        #pragma unroll
        for (int nf = 0; nf < 8; ++nf) {
            float p0 = __expf(s[nf][0] - m0);
            float p1 = __expf(s[nf][1] - m0);
            float p2 = __expf(s[nf][2] - m1);
            float p3 = __expf(s[nf][3] - m1);
            l0 += p0 + p1;
            l1 += p2 + p3;
            uint32_t u0 = f2tf32(p0), u1 = f2tf32(p1);
            uint32_t u2 = f2tf32(p2), u3 = f2tf32(p3);
            uint32_t a00 = __shfl_sync(0xffffffff, u0, src1);
            uint32_t a01 = __shfl_sync(0xffffffff, u1, src1);
            uint32_t a10 = __shfl_sync(0xffffffff, u0, src2);
            uint32_t a11 = __shfl_sync(0xffffffff, u1, src2);
            pa[nf][0] = (tig & 1) ? a01 : a00;
            pa[nf][2] = (tig & 1) ? a11 : a10;
            a00 = __shfl_sync(0xffffffff, u2, src1);
            a01 = __shfl_sync(0xffffffff, u3, src1);
            a10 = __shfl_sync(0xffffffff, u2, src2);
            a11 = __shfl_sync(0xffffffff, u3, src2);
            pa[nf][1] = (tig & 1) ? a01 : a00;
            pa[nf][3] = (tig & 1) ? a11 : a10;
        }

        #pragma unroll
        for (int kt2 = 0; kt2 < 8; ++kt2) {
            const uint32_t* vr0 = (const uint32_t*)(vt_ + (8 * kt2 + tig) * APi + g);
            const uint32_t* vr1 = (const uint32_t*)(vt_ + (8 * kt2 + tig + 4) * APi + g);
            #pragma unroll
            for (int df = 0; df < 8; ++df) {
                uint32_t bf[2];
                bf[0] = vr0[8 * df];
                bf[1] = vr1[8 * df];
                mma_tf32(o[df], pa[kt2], bf);
            }
        }

        __syncthreads();
        if (it + 2 < NT) load_tile(it + 2, st);
        else             CP_COMMIT();
    }

    l0 += __shfl_xor_sync(0xffffffff, l0, 1);
    l0 += __shfl_xor_sync(0xffffffff, l0, 2);
    l1 += __shfl_xor_sync(0xffffffff, l1, 1);
    l1 += __shfl_xor_sync(0xffffffff, l1, 2);
    const float inv0 = 1.f / l0, inv1 = 1.f / l1;
    const int qr0 = q0 + wq + g;
    const int qr1 = qr0 + 8;
    #pragma unroll
    for (int df = 0; df < 8; ++df) {
        *(__half2*)(ctx + (tok0 + qr0) * Cc_ + hoff + 8 * df + 2 * tig) =
            __floats2half2_rn(o[df][0] * inv0, o[df][1] * inv0);
        *(__half2*)(ctx + (tok0 + qr1) * Cc_ + hoff + 8 * df + 2 * tig) =
            __floats2half2_rn(o[df][2] * inv1, o[df][3] * inv1);
    }
}

// ---------------------------------------------------------------------------
// out[row] = res[row] + LayerNorm(x[row]) * w + b     (row length 1024)
// DUAL=1: also write __half copy to out_h.
// ---------------------------------------------------------------------------
template<int DUAL>
__global__ __launch_bounds__(256)
void ln_residual(const float* __restrict__ x, const float* __restrict__ res,
                 const float* __restrict__ w, const float* __restrict__ bp,
                 float* __restrict__ out, __half* __restrict__ out_h)
{
    __shared__ float red[256];
    const int row = blockIdx.x;
    const int tid = threadIdx.x;
    const size_t base = (size_t)row * Cc_;

    float4 v = *(const float4*)(x + base + tid * 4);
    float s = v.x + v.y + v.z + v.w;
    red[tid] = s;
    __syncthreads();
    #pragma unroll
    for (int off = 128; off > 0; off >>= 1) {
        if (tid < off) red[tid] += red[tid + off];
        __syncthreads();
    }
    const float mu = red[0] * (1.0f / Cc_);
    __syncthreads();

    float d0 = v.x - mu, d1 = v.y - mu, d2 = v.z - mu, d3 = v.w - mu;
    red[tid] = d0*d0 + d1*d1 + d2*d2 + d3*d3;
    __syncthreads();
    #pragma unroll
    for (int off = 128; off > 0; off >>= 1) {
        if (tid < off) red[tid] += red[tid + off];
        __syncthreads();
    }
    const float var  = red[0] * (1.0f / Cc_);
    const float rstd = rsqrtf(var + 1e-5f);

    float4 rv = *(const float4*)(res + base + tid * 4);
    float4 wv = *(const float4*)(w + tid * 4);
    float4 bv = *(const float4*)(bp + tid * 4);
    float4 ov;
    ov.x = rv.x + d0 * rstd * wv.x + bv.x;
    ov.y = rv.y + d1 * rstd * wv.y + bv.y;
    ov.z = rv.z + d2 * rstd * wv.z + bv.z;
    ov.w = rv.w + d3 * rstd * wv.w + bv.w;
    *(float4*)(out + base + tid * 4) = ov;
    if (DUAL == 1) {
        __half2* oh = (__half2*)(out_h + base + tid * 4);
        oh[0] = __floats2half2_rn(ov.x, ov.y);
        oh[1] = __floats2half2_rn(ov.z, ov.w);
    }
}

// ---------------------------------------------------------------------------
// Launch
// ---------------------------------------------------------------------------
extern "C" void kernel_launch(void* const* d_in, const int* in_sizes, int n_in,
                              void* d_out, int out_size)
{
    const float* x      = (const float*)d_in[0];
    const float* qkv_w  = (const float*)d_in[1];
    const float* proj_w = (const float*)d_in[2];
    const float* proj_b = (const float*)d_in[3];
    const float* ln1_w  = (const float*)d_in[4];
    const float* ln1_b  = (const float*)d_in[5];
    const float* fc1_w  = (const float*)d_in[6];
    const float* fc1_b  = (const float*)d_in[7];
    const float* fc2_w  = (const float*)d_in[8];
    const float* fc2_b  = (const float*)d_in[9];
    const float* ln2_w  = (const float*)d_in[10];
    const float* ln2_b  = (const float*)d_in[11];
    float* out = (float*)d_out;

    float *qkv, *res, *mlp;
    __half *ctx, *resr, *hbuf, *xh, *w1, *w2, *w3, *w4;
    cudaGetSymbolAddress((void**)&qkv,  g_qkv);
    cudaGetSymbolAddress((void**)&ctx,  g_ctx);
    cudaGetSymbolAddress((void**)&res,  g_res);
    cudaGetSymbolAddress((void**)&resr, g_resr);
    cudaGetSymbolAddress((void**)&hbuf, g_h);
    cudaGetSymbolAddress((void**)&mlp,  g_mlp);
    cudaGetSymbolAddress((void**)&xh,   g_xh);
    cudaGetSymbolAddress((void**)&w1,   g_w1);
    cudaGetSymbolAddress((void**)&w2,   g_w2);
    cudaGetSymbolAddress((void**)&w3,   g_w3);
    cudaGetSymbolAddress((void**)&w4,   g_w4);

    cudaFuncSetAttribute(h_gemm<0,0>,
        cudaFuncAttributeMaxDynamicSharedMemorySize, GEMM_SMEM);
    cudaFuncSetAttribute(h_gemm<0,1>,
        cudaFuncAttributeMaxDynamicSharedMemorySize, GEMM_SMEM);
    cudaFuncSetAttribute(h_gemm<1,2>,
        cudaFuncAttributeMaxDynamicSharedMemorySize, GEMM_SMEM);
    cudaFuncSetAttribute(attn_mma,
        cudaFuncAttributeMaxDynamicSharedMemorySize, ATT_SMEM);

    // 0) producer-side fp16 conversion of GEMM operands
    auto hl = [](const float* src, __half* dst, size_t n) {
        int n4 = (int)(n / 4);
        to_half<<<(n4 + 255) / 256, 256>>>(src, dst, n4);
    };
    hl(x,      xh, (size_t)MTOK * Cc_);
    hl(qkv_w,  w1, (size_t)3 * Cc_ * Cc_);
    hl(proj_w, w2, (size_t)Cc_ * Cc_);
    hl(fc1_w,  w3, (size_t)HID * Cc_);
    hl(fc2_w,  w4, (size_t)Cc_ * HID);

    // 1) qkv = x @ qkv_w^T  (fp32 out, tf32-rounded for attention)
    h_gemm<0,1><<<dim3(3 * Cc_ / GBN, MTOK / GBM), 256, GEMM_SMEM>>>(
        xh, w1, nullptr, qkv, MTOK, 3 * Cc_, Cc_);
    // 2) attention -> ctx (half)
    attn_mma<<<dim3(Nn / AQ, Hh, Bb), 256, ATT_SMEM>>>(qkv, ctx);
    // 3) res = ctx @ proj_w^T + proj_b  (fp32 residual base)
    h_gemm<0,0><<<dim3(Cc_ / GBN, MTOK / GBM), 256, GEMM_SMEM>>>(
        ctx, w2, proj_b, res, MTOK, Cc_, Cc_);
    // 4) res = res + LN(res); also half copy resr
    ln_residual<1><<<MTOK, 256>>>(res, res, ln1_w, ln1_b, res, resr);
    // 5) h = gelu(resr @ fc1_w^T + fc1_b)  (half out)
    h_gemm<1,2><<<dim3(HID / GBN, MTOK / GBM), 256, GEMM_SMEM>>>(
        resr, w3, fc1_b, hbuf, MTOK, HID, Cc_);
    // 6) mlp = h @ fc2_w^T + fc2_b  (fp32 out)
    h_gemm<0,0><<<dim3(Cc_ / GBN, MTOK / GBM), 256, GEMM_SMEM>>>(
        hbuf, w4, fc2_b, mlp, MTOK, Cc_, HID);
    // 7) out = res + LN(mlp)
    ln_residual<0><<<MTOK, 256>>>(mlp, res, ln2_w, ln2_b, out, nullptr);
}

// round 9
// speedup vs baseline: 7.0877x; 1.4292x over previous
#include <cuda_runtime.h>
#include <cuda_fp16.h>
#include <math.h>
#include <stdint.h>

// Problem constants
constexpr int Bb   = 2;
constexpr int Nn   = 2048;
constexpr int Cc_  = 1024;
constexpr int Hh   = 16;
constexpr int HD   = 64;
constexpr int HID  = 4096;
constexpr int MTOK = Bb * Nn;            // 4096 token rows
constexpr float SCALE = 0.125f;          // 64^-0.5

// Scratch (static device allocations; no cudaMalloc allowed)
__device__ __half g_qkv [(size_t)MTOK * 3 * Cc_];   // 24 MB
__device__ __half g_ctx [(size_t)MTOK * Cc_];       //  8 MB
__device__ float  g_res [(size_t)MTOK * Cc_];       // 16 MB fp32 residual
__device__ __half g_resr[(size_t)MTOK * Cc_];       //  8 MB half copy
__device__ __half g_h   [(size_t)MTOK * HID];       // 32 MB
__device__ float  g_mlp [(size_t)MTOK * Cc_];       // 16 MB fp32
__device__ __half g_xh  [(size_t)MTOK * Cc_];       //  8 MB half x
__device__ __half g_w1  [(size_t)3 * Cc_ * Cc_];    //  6 MB
__device__ __half g_w2  [(size_t)Cc_ * Cc_];        //  2 MB
__device__ __half g_w3  [(size_t)HID * Cc_];        //  8 MB
__device__ __half g_w4  [(size_t)Cc_ * HID];        //  8 MB

// ===========================================================================
// helpers
// ===========================================================================
__device__ __forceinline__ uint32_t smem_u32(const void* p) {
    uint32_t a;
    asm("{ .reg .u64 t; cvta.to.shared.u64 t, %1; cvt.u32.u64 %0, t; }"
        : "=r"(a) : "l"(p));
    return a;
}
__device__ __forceinline__ void cp_async16(uint32_t dst, const void* src) {
    asm volatile("cp.async.cg.shared.global [%0], [%1], 16;"
                 :: "r"(dst), "l"(src));
}
#define CP_COMMIT() asm volatile("cp.async.commit_group;" ::: "memory")
#define CP_WAIT1()  asm volatile("cp.async.wait_group 1;" ::: "memory")
#define CP_WAIT2()  asm volatile("cp.async.wait_group 2;" ::: "memory")

#define LDSM4(r, a) \
    asm volatile("ldmatrix.sync.aligned.m8n8.x4.shared.b16 {%0,%1,%2,%3}, [%4];" \
        : "=r"((r)[0]), "=r"((r)[1]), "=r"((r)[2]), "=r"((r)[3]) : "r"(a))
#define LDSM2(r, a) \
    asm volatile("ldmatrix.sync.aligned.m8n8.x2.shared.b16 {%0,%1}, [%2];" \
        : "=r"((r)[0]), "=r"((r)[1]) : "r"(a))
#define LDSM2T(r, a) \
    asm volatile("ldmatrix.sync.aligned.m8n8.x2.trans.shared.b16 {%0,%1}, [%2];" \
        : "=r"((r)[0]), "=r"((r)[1]) : "r"(a))

// bit-reinterpret __half2 -> uint32_t (compiles to nothing)
__device__ __forceinline__ uint32_t h2_as_u32(__half2 h) {
    uint32_t u;
    *reinterpret_cast<__half2*>(&u) = h;
    return u;
}

// mma.sync m16n8k16 f16, fp32 accumulate
__device__ __forceinline__ void mma_f16(float* c, const uint32_t* a,
                                        const uint32_t* b) {
    asm volatile(
        "mma.sync.aligned.m16n8k16.row.col.f32.f16.f16.f32 "
        "{%0,%1,%2,%3}, {%4,%5,%6,%7}, {%8,%9}, {%0,%1,%2,%3};"
        : "+f"(c[0]), "+f"(c[1]), "+f"(c[2]), "+f"(c[3])
        : "r"(a[0]), "r"(a[1]), "r"(a[2]), "r"(a[3]),
          "r"(b[0]), "r"(b[1]));
}

__device__ __forceinline__ float gelu_exact(float v) {
    return 0.5f * v * (1.0f + erff(v * 0.70710678118654752f));
}

// ---------------------------------------------------------------------------
// Elementwise fp16 conversion pass
// ---------------------------------------------------------------------------
__global__ __launch_bounds__(256)
void to_half(const float* __restrict__ in, __half* __restrict__ out, int n4)
{
    int i = blockIdx.x * 256 + threadIdx.x;
    if (i >= n4) return;
    float4 v = ((const float4*)in)[i];
    __half2* o2 = (__half2*)out;
    o2[2 * i + 0] = __floats2half2_rn(v.x, v.y);
    o2[2 * i + 1] = __floats2half2_rn(v.z, v.w);
}

// ===========================================================================
// fp16 mma.sync GEMM (NT) with ldmatrix fragment loads.
// C[M,N] = A[M,K] @ B[N,K]^T (+bias)(+gelu). BM=BN=128, BK=64 halves,
// 256 threads (8 warps 2x4), warp tile 64x32, pitch 72 halves (144B).
// OUT: 0 = f32, 2 = f16.
// ===========================================================================
constexpr int GBM = 128, GBN = 128, HBK = 64;
constexpr int HPITCH = HBK + 8;                     // 72 halves = 144 B
constexpr int STAGE_H = GBM * HPITCH;
constexpr int GEMM_SMEM = 2 * 2 * STAGE_H * 2;      // 73728 B

template<int EPI, int OUT>
__global__ __launch_bounds__(256, 2)
void h_gemm(const __half* __restrict__ A, const __half* __restrict__ Bw,
            const float* __restrict__ bias, void* __restrict__ Co,
            int M, int N, int K)
{
    extern __shared__ __half smemh[];
    __half* As = smemh;
    __half* Bs = smemh + 2 * STAGE_H;
    const uint32_t As_u = smem_u32(As);
    const uint32_t Bs_u = smem_u32(Bs);

    const int tid = threadIdx.x;
    const int wid = tid >> 5;
    const int lid = tid & 31;
    const int g   = lid >> 2;
    const int tig = lid & 3;
    const int wm  = (wid & 1) * 64;
    const int wn  = (wid >> 1) * 32;
    const int m0  = blockIdx.y * GBM;
    const int n0  = blockIdx.x * GBN;
    const int NC  = K / HBK;

    // ldmatrix lane addressing (byte offsets within a stage)
    const uint32_t a_lane = (uint32_t)((wm + (lid & 15)) * 144 + (lid >> 4) * 16);
    const uint32_t b_lane = (uint32_t)((wn + (lid & 7)) * 144 + ((lid >> 3) & 1) * 16);

    float acc[4][4][4];
    #pragma unroll
    for (int i = 0; i < 4; ++i)
        #pragma unroll
        for (int j = 0; j < 4; ++j)
            #pragma unroll
            for (int t = 0; t < 4; ++t) acc[i][j][t] = 0.f;

    auto load_chunk = [&](int kc, int st) {
        const int k0h = kc * HBK;
        const uint32_t abase = As_u + st * STAGE_H * 2;
        const uint32_t bbase = Bs_u + st * STAGE_H * 2;
        #pragma unroll
        for (int t = 0; t < 4; ++t) {
            int idx = tid + t * 256;
            int r   = idx >> 3;
            int c   = idx & 7;
            uint32_t off = (uint32_t)(r * 144 + c * 16);
            cp_async16(abase + off, A + (size_t)(m0 + r) * K + k0h + c * 8);
            cp_async16(bbase + off, Bw + (size_t)(n0 + r) * K + k0h + c * 8);
        }
        CP_COMMIT();
    };

    load_chunk(0, 0);
    load_chunk(1, 1);

    for (int i = 0; i < NC; ++i) {
        const int st = i & 1;
        CP_WAIT1();
        __syncthreads();

        const uint32_t Ast = As_u + st * STAGE_H * 2;
        const uint32_t Bst = Bs_u + st * STAGE_H * 2;

        #pragma unroll
        for (int kk = 0; kk < 4; ++kk) {           // 4 x K=16
            uint32_t af[4][4], bf[4][2];
            #pragma unroll
            for (int mf = 0; mf < 4; ++mf)
                LDSM4(af[mf], Ast + a_lane + mf * 16 * 144 + kk * 32);
            #pragma unroll
            for (int nf = 0; nf < 4; ++nf)
                LDSM2(bf[nf], Bst + b_lane + nf * 8 * 144 + kk * 32);
            #pragma unroll
            for (int mf = 0; mf < 4; ++mf)
                #pragma unroll
                for (int nf = 0; nf < 4; ++nf)
                    mma_f16(acc[mf][nf], af[mf], bf[nf]);
        }

        __syncthreads();
        if (i + 2 < NC) load_chunk(i + 2, st);
        else            CP_COMMIT();
    }

    #pragma unroll
    for (int mf = 0; mf < 4; ++mf) {
        const int r0 = m0 + wm + mf * 16 + g;
        const int r1 = r0 + 8;
        #pragma unroll
        for (int nf = 0; nf < 4; ++nf) {
            const int col = n0 + wn + nf * 8 + tig * 2;
            float b0 = 0.f, b1 = 0.f;
            if (bias) { b0 = bias[col]; b1 = bias[col + 1]; }
            float t0 = acc[mf][nf][0] + b0;
            float t1 = acc[mf][nf][1] + b1;
            float t2 = acc[mf][nf][2] + b0;
            float t3 = acc[mf][nf][3] + b1;
            if (EPI == 1) {
                t0 = gelu_exact(t0); t1 = gelu_exact(t1);
                t2 = gelu_exact(t2); t3 = gelu_exact(t3);
            }
            if (OUT == 0) {
                float* Cf = (float*)Co;
                float2 v0; v0.x = t0; v0.y = t1;
                float2 v1; v1.x = t2; v1.y = t3;
                *(float2*)(Cf + (size_t)r0 * N + col) = v0;
                *(float2*)(Cf + (size_t)r1 * N + col) = v1;
            } else {
                __half* Ch = (__half*)Co;
                *(__half2*)(Ch + (size_t)r0 * N + col) = __floats2half2_rn(t0, t1);
                *(__half2*)(Ch + (size_t)r1 * N + col) = __floats2half2_rn(t2, t3);
            }
        }
    }
}

// ===========================================================================
// Flash attention, fp16 m16n8k16 throughout. qkv is __half [tok][3C].
// 128 q rows/CTA (8 warps x 16), 64-key tiles double-buffered, pitch 72 h.
// ===========================================================================
constexpr int AQ   = 128;
constexpr int AKT  = 64;
constexpr int APiH = 72;
constexpr int A_KOFF = AQ * APiH;                   // halves
constexpr int A_VOFF = A_KOFF + 2 * AKT * APiH;
constexpr int ATT_SMEM = (A_VOFF + 2 * AKT * APiH) * 2;   // 55296 B

__global__ __launch_bounds__(256, 2)
void attn_h(const __half* __restrict__ qkv, __half* __restrict__ ctx)
{
    extern __shared__ __half smh[];
    __half* Qs = smh;
    __half* Ks = smh + A_KOFF;
    __half* Vs = smh + A_VOFF;
    const uint32_t Qs_u = smem_u32(Qs);
    const uint32_t Ks_u = smem_u32(Ks);
    const uint32_t Vs_u = smem_u32(Vs);

    const int tid = threadIdx.x;
    const int wid = tid >> 5;
    const int lid = tid & 31;
    const int g   = lid >> 2;
    const int tig = lid & 3;
    const int q0  = blockIdx.x * AQ;
    const int h   = blockIdx.y;
    const int b   = blockIdx.z;
    const int wq  = wid * 16;

    const size_t tok0 = (size_t)(b * Nn);
    const int hoff = h * HD;

    // ldmatrix lane addressing (byte offsets)
    const uint32_t q_lane = (uint32_t)((wq + (lid & 15)) * 144 + (lid >> 4) * 16);
    const uint32_t k_lane = (uint32_t)((lid & 7) * 144 + ((lid >> 3) & 1) * 16);
    const uint32_t v_lane = (uint32_t)((lid & 15) * 144);

    // Q tile: 128 rows x 8 chunks = 1024; 4/thread
    #pragma unroll
    for (int t = 0; t < 4; ++t) {
        int idx = tid + t * 256;
        int r = idx >> 3, c = idx & 7;
        cp_async16(Qs_u + (uint32_t)(r * 144 + c * 16),
                   qkv + (tok0 + q0 + r) * (3 * Cc_) + hoff + c * 8);
    }
    CP_COMMIT();

    auto load_tile = [&](int kt, int st) {
        const int k0 = kt * AKT;
        const uint32_t kb = Ks_u + (uint32_t)(st * AKT * APiH) * 2;
        const uint32_t vb = Vs_u + (uint32_t)(st * AKT * APiH) * 2;
        #pragma unroll
        for (int t = 0; t < 2; ++t) {
            int idx = tid + t * 256;
            int r = idx >> 3, c = idx & 7;
            const __half* src = qkv + (tok0 + k0 + r) * (3 * Cc_) + Cc_ + hoff + c * 8;
            uint32_t off = (uint32_t)(r * 144 + c * 16);
            cp_async16(kb + off, src);
            cp_async16(vb + off, src + Cc_);
        }
        CP_COMMIT();
    };
    load_tile(0, 0);
    load_tile(1, 1);

    CP_WAIT2();
    __syncthreads();

    // Q fragments: 4 chunks of K=16
    uint32_t qf[4][4];
    #pragma unroll
    for (int kk = 0; kk < 4; ++kk)
        LDSM4(qf[kk], Qs_u + q_lane + kk * 32);

    float o[8][4];
    #pragma unroll
    for (int d = 0; d < 8; ++d)
        #pragma unroll
        for (int t = 0; t < 4; ++t) o[d][t] = 0.f;
    float m0 = -1e30f, m1 = -1e30f, l0 = 0.f, l1 = 0.f;

    const int NT = Nn / AKT;     // 32
    for (int it = 0; it < NT; ++it) {
        const int st = it & 1;
        CP_WAIT1();
        __syncthreads();

        const uint32_t Kb = Ks_u + (uint32_t)(st * AKT * APiH) * 2;
        const uint32_t Vb = Vs_u + (uint32_t)(st * AKT * APiH) * 2;

        // ---- S = Q K^T  (8 key-chunks of 8) ----
        float s[8][4];
        #pragma unroll
        for (int nf = 0; nf < 8; ++nf) {
            s[nf][0] = 0.f; s[nf][1] = 0.f; s[nf][2] = 0.f; s[nf][3] = 0.f;
            const uint32_t kaddr = Kb + k_lane + nf * 8 * 144;
            #pragma unroll
            for (int kk = 0; kk < 4; ++kk) {
                uint32_t bf[2];
                LDSM2(bf, kaddr + kk * 32);
                mma_f16(s[nf], qf[kk], bf);
            }
            s[nf][0] *= SCALE; s[nf][1] *= SCALE;
            s[nf][2] *= SCALE; s[nf][3] *= SCALE;
        }

        // ---- softmax update ----
        float t0 = -1e30f, t1 = -1e30f;
        #pragma unroll
        for (int nf = 0; nf < 8; ++nf) {
            t0 = fmaxf(t0, fmaxf(s[nf][0], s[nf][1]));
            t1 = fmaxf(t1, fmaxf(s[nf][2], s[nf][3]));
        }
        t0 = fmaxf(t0, __shfl_xor_sync(0xffffffff, t0, 1));
        t0 = fmaxf(t0, __shfl_xor_sync(0xffffffff, t0, 2));
        t1 = fmaxf(t1, __shfl_xor_sync(0xffffffff, t1, 1));
        t1 = fmaxf(t1, __shfl_xor_sync(0xffffffff, t1, 2));
        const float nm0 = fmaxf(m0, t0), nm1 = fmaxf(m1, t1);
        const float c0 = __expf(m0 - nm0), c1 = __expf(m1 - nm1);
        m0 = nm0; m1 = nm1;
        l0 *= c0; l1 *= c1;
        #pragma unroll
        for (int d = 0; d < 8; ++d) {
            o[d][0] *= c0; o[d][1] *= c0;
            o[d][2] *= c1; o[d][3] *= c1;
        }

        // ---- P = exp(S-m) packed directly into k16 A-fragments ----
        uint32_t pa[4][4];
        #pragma unroll
        for (int nf = 0; nf < 8; ++nf) {
            float p0 = __expf(s[nf][0] - m0);
            float p1 = __expf(s[nf][1] - m0);
            float p2 = __expf(s[nf][2] - m1);
            float p3 = __expf(s[nf][3] - m1);
            l0 += p0 + p1;
            l1 += p2 + p3;
            pa[nf >> 1][2 * (nf & 1) + 0] = h2_as_u32(__floats2half2_rn(p0, p1));
            pa[nf >> 1][2 * (nf & 1) + 1] = h2_as_u32(__floats2half2_rn(p2, p3));
        }

        // ---- O += P V  (V^T fragments via ldmatrix.trans) ----
        #pragma unroll
        for (int kt2 = 0; kt2 < 4; ++kt2) {
            const uint32_t vbase = Vb + v_lane + kt2 * 16 * 144;
            #pragma unroll
            for (int df = 0; df < 8; ++df) {
                uint32_t bf[2];
                LDSM2T(bf, vbase + df * 16);
                mma_f16(o[df], pa[kt2], bf);
            }
        }

        __syncthreads();
        if (it + 2 < NT) load_tile(it + 2, st);
        else             CP_COMMIT();
    }

    l0 += __shfl_xor_sync(0xffffffff, l0, 1);
    l0 += __shfl_xor_sync(0xffffffff, l0, 2);
    l1 += __shfl_xor_sync(0xffffffff, l1, 1);
    l1 += __shfl_xor_sync(0xffffffff, l1, 2);
    const float inv0 = 1.f / l0, inv1 = 1.f / l1;
    const int qr0 = q0 + wq + g;
    const int qr1 = qr0 + 8;
    #pragma unroll
    for (int df = 0; df < 8; ++df) {
        *(__half2*)(ctx + (tok0 + qr0) * Cc_ + hoff + 8 * df + 2 * tig) =
            __floats2half2_rn(o[df][0] * inv0, o[df][1] * inv0);
        *(__half2*)(ctx + (tok0 + qr1) * Cc_ + hoff + 8 * df + 2 * tig) =
            __floats2half2_rn(o[df][2] * inv1, o[df][3] * inv1);
    }
}

// ---------------------------------------------------------------------------
// out[row] = res[row] + LayerNorm(x[row]) * w + b     (row length 1024)
// DUAL=1: also write __half copy to out_h.
// ---------------------------------------------------------------------------
template<int DUAL>
__global__ __launch_bounds__(256)
void ln_residual(const float* __restrict__ x, const float* __restrict__ res,
                 const float* __restrict__ w, const float* __restrict__ bp,
                 float* __restrict__ out, __half* __restrict__ out_h)
{
    __shared__ float red[256];
    const int row = blockIdx.x;
    const int tid = threadIdx.x;
    const size_t base = (size_t)row * Cc_;

    float4 v = *(const float4*)(x + base + tid * 4);
    float s = v.x + v.y + v.z + v.w;
    red[tid] = s;
    __syncthreads();
    #pragma unroll
    for (int off = 128; off > 0; off >>= 1) {
        if (tid < off) red[tid] += red[tid + off];
        __syncthreads();
    }
    const float mu = red[0] * (1.0f / Cc_);
    __syncthreads();

    float d0 = v.x - mu, d1 = v.y - mu, d2 = v.z - mu, d3 = v.w - mu;
    red[tid] = d0*d0 + d1*d1 + d2*d2 + d3*d3;
    __syncthreads();
    #pragma unroll
    for (int off = 128; off > 0; off >>= 1) {
        if (tid < off) red[tid] += red[tid + off];
        __syncthreads();
    }
    const float var  = red[0] * (1.0f / Cc_);
    const float rstd = rsqrtf(var + 1e-5f);

    float4 rv = *(const float4*)(res + base + tid * 4);
    float4 wv = *(const float4*)(w + tid * 4);
    float4 bv = *(const float4*)(bp + tid * 4);
    float4 ov;
    ov.x = rv.x + d0 * rstd * wv.x + bv.x;
    ov.y = rv.y + d1 * rstd * wv.y + bv.y;
    ov.z = rv.z + d2 * rstd * wv.z + bv.z;
    ov.w = rv.w + d3 * rstd * wv.w + bv.w;
    *(float4*)(out + base + tid * 4) = ov;
    if (DUAL == 1) {
        __half2* oh = (__half2*)(out_h + base + tid * 4);
        oh[0] = __floats2half2_rn(ov.x, ov.y);
        oh[1] = __floats2half2_rn(ov.z, ov.w);
    }
}

// ---------------------------------------------------------------------------
// Launch
// ---------------------------------------------------------------------------
extern "C" void kernel_launch(void* const* d_in, const int* in_sizes, int n_in,
                              void* d_out, int out_size)
{
    const float* x      = (const float*)d_in[0];
    const float* qkv_w  = (const float*)d_in[1];
    const float* proj_w = (const float*)d_in[2];
    const float* proj_b = (const float*)d_in[3];
    const float* ln1_w  = (const float*)d_in[4];
    const float* ln1_b  = (const float*)d_in[5];
    const float* fc1_w  = (const float*)d_in[6];
    const float* fc1_b  = (const float*)d_in[7];
    const float* fc2_w  = (const float*)d_in[8];
    const float* fc2_b  = (const float*)d_in[9];
    const float* ln2_w  = (const float*)d_in[10];
    const float* ln2_b  = (const float*)d_in[11];
    float* out = (float*)d_out;

    float *res, *mlp;
    __half *qkv, *ctx, *resr, *hbuf, *xh, *w1, *w2, *w3, *w4;
    cudaGetSymbolAddress((void**)&qkv,  g_qkv);
    cudaGetSymbolAddress((void**)&ctx,  g_ctx);
    cudaGetSymbolAddress((void**)&res,  g_res);
    cudaGetSymbolAddress((void**)&resr, g_resr);
    cudaGetSymbolAddress((void**)&hbuf, g_h);
    cudaGetSymbolAddress((void**)&mlp,  g_mlp);
    cudaGetSymbolAddress((void**)&xh,   g_xh);
    cudaGetSymbolAddress((void**)&w1,   g_w1);
    cudaGetSymbolAddress((void**)&w2,   g_w2);
    cudaGetSymbolAddress((void**)&w3,   g_w3);
    cudaGetSymbolAddress((void**)&w4,   g_w4);

    cudaFuncSetAttribute(h_gemm<0,0>,
        cudaFuncAttributeMaxDynamicSharedMemorySize, GEMM_SMEM);
    cudaFuncSetAttribute(h_gemm<0,2>,
        cudaFuncAttributeMaxDynamicSharedMemorySize, GEMM_SMEM);
    cudaFuncSetAttribute(h_gemm<1,2>,
        cudaFuncAttributeMaxDynamicSharedMemorySize, GEMM_SMEM);
    cudaFuncSetAttribute(attn_h,
        cudaFuncAttributeMaxDynamicSharedMemorySize, ATT_SMEM);

    // 0) producer-side fp16 conversion of GEMM operands
    auto hl = [](const float* src, __half* dst, size_t n) {
        int n4 = (int)(n / 4);
        to_half<<<(n4 + 255) / 256, 256>>>(src, dst, n4);
    };
    hl(x,      xh, (size_t)MTOK * Cc_);
    hl(qkv_w,  w1, (size_t)3 * Cc_ * Cc_);
    hl(proj_w, w2, (size_t)Cc_ * Cc_);
    hl(fc1_w,  w3, (size_t)HID * Cc_);
    hl(fc2_w,  w4, (size_t)Cc_ * HID);

    // 1) qkv = x @ qkv_w^T  (half out)
    h_gemm<0,2><<<dim3(3 * Cc_ / GBN, MTOK / GBM), 256, GEMM_SMEM>>>(
        xh, w1, nullptr, qkv, MTOK, 3 * Cc_, Cc_);
    // 2) attention -> ctx (half)
    attn_h<<<dim3(Nn / AQ, Hh, Bb), 256, ATT_SMEM>>>(qkv, ctx);
    // 3) res = ctx @ proj_w^T + proj_b  (fp32 residual base)
    h_gemm<0,0><<<dim3(Cc_ / GBN, MTOK / GBM), 256, GEMM_SMEM>>>(
        ctx, w2, proj_b, res, MTOK, Cc_, Cc_);
    // 4) res = res + LN(res); also half copy resr
    ln_residual<1><<<MTOK, 256>>>(res, res, ln1_w, ln1_b, res, resr);
    // 5) h = gelu(resr @ fc1_w^T + fc1_b)  (half out)
    h_gemm<1,2><<<dim3(HID / GBN, MTOK / GBM), 256, GEMM_SMEM>>>(
        resr, w3, fc1_b, hbuf, MTOK, HID, Cc_);
    // 6) mlp = h @ fc2_w^T + fc2_b  (fp32 out)
    h_gemm<0,0><<<dim3(Cc_ / GBN, MTOK / GBM), 256, GEMM_SMEM>>>(
        hbuf, w4, fc2_b, mlp, MTOK, Cc_, HID);
    // 7) out = res + LN(mlp)
    ln_residual<0><<<MTOK, 256>>>(mlp, res, ln2_w, ln2_b, out, nullptr);
}

// round 10
// speedup vs baseline: 7.1837x; 1.0135x over previous
#include <cuda_runtime.h>
#include <cuda_fp16.h>
#include <math.h>
#include <stdint.h>

// Problem constants
constexpr int Bb   = 2;
constexpr int Nn   = 2048;
constexpr int Cc_  = 1024;
constexpr int Hh   = 16;
constexpr int HD   = 64;
constexpr int HID  = 4096;
constexpr int MTOK = Bb * Nn;            // 4096 token rows
constexpr float SCALE = 0.125f;          // 64^-0.5

// Scratch (static device allocations; no cudaMalloc allowed)
__device__ __half g_qkv [(size_t)MTOK * 3 * Cc_];   // 24 MB
__device__ __half g_ctx [(size_t)MTOK * Cc_];       //  8 MB
__device__ float  g_res [(size_t)MTOK * Cc_];       // 16 MB fp32 residual
__device__ __half g_resr[(size_t)MTOK * Cc_];       //  8 MB half copy
__device__ __half g_h   [(size_t)MTOK * HID];       // 32 MB
__device__ float  g_mlp [(size_t)MTOK * Cc_];       // 16 MB fp32
__device__ __half g_xh  [(size_t)MTOK * Cc_];       //  8 MB half x
__device__ __half g_w1  [(size_t)3 * Cc_ * Cc_];    //  6 MB
__device__ __half g_w2  [(size_t)Cc_ * Cc_];        //  2 MB
__device__ __half g_w3  [(size_t)HID * Cc_];        //  8 MB
__device__ __half g_w4  [(size_t)Cc_ * HID];        //  8 MB

// ===========================================================================
// helpers
// ===========================================================================
__device__ __forceinline__ uint32_t smem_u32(const void* p) {
    uint32_t a;
    asm("{ .reg .u64 t; cvta.to.shared.u64 t, %1; cvt.u32.u64 %0, t; }"
        : "=r"(a) : "l"(p));
    return a;
}
__device__ __forceinline__ void cp_async16(uint32_t dst, const void* src) {
    asm volatile("cp.async.cg.shared.global [%0], [%1], 16;"
                 :: "r"(dst), "l"(src));
}
#define CP_COMMIT() asm volatile("cp.async.commit_group;" ::: "memory")
#define CP_WAIT1()  asm volatile("cp.async.wait_group 1;" ::: "memory")
#define CP_WAIT2()  asm volatile("cp.async.wait_group 2;" ::: "memory")

#define LDSM4(r, a) \
    asm volatile("ldmatrix.sync.aligned.m8n8.x4.shared.b16 {%0,%1,%2,%3}, [%4];" \
        : "=r"((r)[0]), "=r"((r)[1]), "=r"((r)[2]), "=r"((r)[3]) : "r"(a))
#define LDSM2(r, a) \
    asm volatile("ldmatrix.sync.aligned.m8n8.x2.shared.b16 {%0,%1}, [%2];" \
        : "=r"((r)[0]), "=r"((r)[1]) : "r"(a))
#define LDSM2T(r, a) \
    asm volatile("ldmatrix.sync.aligned.m8n8.x2.trans.shared.b16 {%0,%1}, [%2];" \
        : "=r"((r)[0]), "=r"((r)[1]) : "r"(a))

// bit-reinterpret __half2 -> uint32_t (compiles to nothing)
__device__ __forceinline__ uint32_t h2_as_u32(__half2 h) {
    uint32_t u;
    *reinterpret_cast<__half2*>(&u) = h;
    return u;
}

// mma.sync m16n8k16 f16, fp32 accumulate
__device__ __forceinline__ void mma_f16(float* c, const uint32_t* a,
                                        const uint32_t* b) {
    asm volatile(
        "mma.sync.aligned.m16n8k16.row.col.f32.f16.f16.f32 "
        "{%0,%1,%2,%3}, {%4,%5,%6,%7}, {%8,%9}, {%0,%1,%2,%3};"
        : "+f"(c[0]), "+f"(c[1]), "+f"(c[2]), "+f"(c[3])
        : "r"(a[0]), "r"(a[1]), "r"(a[2]), "r"(a[3]),
          "r"(b[0]), "r"(b[1]));
}

__device__ __forceinline__ float gelu_exact(float v) {
    return 0.5f * v * (1.0f + erff(v * 0.70710678118654752f));
}

// ---------------------------------------------------------------------------
// Fused fp16 conversion: all 5 operand tensors in ONE launch.
// Segment boundaries are compile-time constants (float4 units).
// Each thread converts 8 floats (two float4 -> one 16B half store).
// ---------------------------------------------------------------------------
constexpr int C4_X  = MTOK * Cc_ / 4;          // 1048576
constexpr int C4_W1 = 3 * Cc_ * Cc_ / 4;       //  786432
constexpr int C4_W2 = Cc_ * Cc_ / 4;           //  262144
constexpr int C4_W3 = HID * Cc_ / 4;           // 1048576
constexpr int C4_W4 = C4_W3;                   // 1048576
constexpr int C4_B0 = C4_X;
constexpr int C4_B1 = C4_B0 + C4_W1;
constexpr int C4_B2 = C4_B1 + C4_W2;
constexpr int C4_B3 = C4_B2 + C4_W3;
constexpr int C4_TOT = C4_B3 + C4_W4;          // 4194304
constexpr int CONV_BLOCKS = C4_TOT / 2 / 256;  // 8192

__global__ __launch_bounds__(256)
void to_half_all(const float* __restrict__ x,  const float* __restrict__ a1,
                 const float* __restrict__ a2, const float* __restrict__ a3,
                 const float* __restrict__ a4,
                 __half* __restrict__ xo, __half* __restrict__ o1,
                 __half* __restrict__ o2, __half* __restrict__ o3,
                 __half* __restrict__ o4)
{
    const int i8 = blockIdx.x * 256 + threadIdx.x;   // 8-float unit
    const int i4 = i8 * 2;                           // float4 unit (even)
    const float* src; __half* dst; int off4;
    if (i4 < C4_B0)      { src = x;  dst = xo; off4 = i4; }
    else if (i4 < C4_B1) { src = a1; dst = o1; off4 = i4 - C4_B0; }
    else if (i4 < C4_B2) { src = a2; dst = o2; off4 = i4 - C4_B1; }
    else if (i4 < C4_B3) { src = a3; dst = o3; off4 = i4 - C4_B2; }
    else                 { src = a4; dst = o4; off4 = i4 - C4_B3; }
    float4 v0 = ((const float4*)src)[off4];
    float4 v1 = ((const float4*)src)[off4 + 1];
    __half2 h[4];
    h[0] = __floats2half2_rn(v0.x, v0.y);
    h[1] = __floats2half2_rn(v0.z, v0.w);
    h[2] = __floats2half2_rn(v1.x, v1.y);
    h[3] = __floats2half2_rn(v1.z, v1.w);
    *(uint4*)((__half2*)dst + off4 * 2) = *(uint4*)h;
}

// ===========================================================================
// fp16 mma.sync GEMM (NT), ldmatrix fragment loads, 3-stage cp.async pipeline.
// C[M,N] = A[M,K] @ B[N,K]^T (+bias)(+gelu). BM=BN=128, BK=64 halves,
// 256 threads (8 warps 2x4), warp tile 64x32, pitch 72 halves (144B).
// OUT: 0 = f32, 2 = f16.
// ===========================================================================
constexpr int GBM = 128, GBN = 128, HBK = 64;
constexpr int HPITCH = HBK + 8;                     // 72 halves = 144 B
constexpr int STAGE_H = GBM * HPITCH;               // halves per operand stage
constexpr int NSTG = 3;
constexpr int GEMM_SMEM = NSTG * 2 * STAGE_H * 2;   // 110592 B

template<int EPI, int OUT>
__global__ __launch_bounds__(256, 2)
void h_gemm(const __half* __restrict__ A, const __half* __restrict__ Bw,
            const float* __restrict__ bias, void* __restrict__ Co,
            int M, int N, int K)
{
    extern __shared__ __half smemh[];
    __half* As = smemh;
    __half* Bs = smemh + NSTG * STAGE_H;
    const uint32_t As_u = smem_u32(As);
    const uint32_t Bs_u = smem_u32(Bs);

    const int tid = threadIdx.x;
    const int wid = tid >> 5;
    const int lid = tid & 31;
    const int g   = lid >> 2;
    const int tig = lid & 3;
    const int wm  = (wid & 1) * 64;
    const int wn  = (wid >> 1) * 32;
    const int m0  = blockIdx.y * GBM;
    const int n0  = blockIdx.x * GBN;
    const int NC  = K / HBK;

    // ldmatrix lane addressing (byte offsets within a stage)
    const uint32_t a_lane = (uint32_t)((wm + (lid & 15)) * 144 + (lid >> 4) * 16);
    const uint32_t b_lane = (uint32_t)((wn + (lid & 7)) * 144 + ((lid >> 3) & 1) * 16);

    float acc[4][4][4];
    #pragma unroll
    for (int i = 0; i < 4; ++i)
        #pragma unroll
        for (int j = 0; j < 4; ++j)
            #pragma unroll
            for (int t = 0; t < 4; ++t) acc[i][j][t] = 0.f;

    auto load_chunk = [&](int kc, int st) {
        const int k0h = kc * HBK;
        const uint32_t abase = As_u + st * STAGE_H * 2;
        const uint32_t bbase = Bs_u + st * STAGE_H * 2;
        #pragma unroll
        for (int t = 0; t < 4; ++t) {
            int idx = tid + t * 256;
            int r   = idx >> 3;
            int c   = idx & 7;
            uint32_t off = (uint32_t)(r * 144 + c * 16);
            cp_async16(abase + off, A + (size_t)(m0 + r) * K + k0h + c * 8);
            cp_async16(bbase + off, Bw + (size_t)(n0 + r) * K + k0h + c * 8);
        }
        CP_COMMIT();
    };

    load_chunk(0, 0);
    load_chunk(1, 1);
    load_chunk(2, 2);

    int st = 0;
    for (int i = 0; i < NC; ++i) {
        CP_WAIT2();
        __syncthreads();

        const uint32_t Ast = As_u + st * STAGE_H * 2;
        const uint32_t Bst = Bs_u + st * STAGE_H * 2;

        #pragma unroll
        for (int kk = 0; kk < 4; ++kk) {           // 4 x K=16
            uint32_t af[4][4], bf[4][2];
            #pragma unroll
            for (int mf = 0; mf < 4; ++mf)
                LDSM4(af[mf], Ast + a_lane + mf * 16 * 144 + kk * 32);
            #pragma unroll
            for (int nf = 0; nf < 4; ++nf)
                LDSM2(bf[nf], Bst + b_lane + nf * 8 * 144 + kk * 32);
            #pragma unroll
            for (int mf = 0; mf < 4; ++mf)
                #pragma unroll
                for (int nf = 0; nf < 4; ++nf)
                    mma_f16(acc[mf][nf], af[mf], bf[nf]);
        }

        __syncthreads();
        if (i + 3 < NC) load_chunk(i + 3, st);
        else            CP_COMMIT();
        st = (st == NSTG - 1) ? 0 : st + 1;
    }

    #pragma unroll
    for (int mf = 0; mf < 4; ++mf) {
        const int r0 = m0 + wm + mf * 16 + g;
        const int r1 = r0 + 8;
        #pragma unroll
        for (int nf = 0; nf < 4; ++nf) {
            const int col = n0 + wn + nf * 8 + tig * 2;
            float b0 = 0.f, b1 = 0.f;
            if (bias) { b0 = bias[col]; b1 = bias[col + 1]; }
            float t0 = acc[mf][nf][0] + b0;
            float t1 = acc[mf][nf][1] + b1;
            float t2 = acc[mf][nf][2] + b0;
            float t3 = acc[mf][nf][3] + b1;
            if (EPI == 1) {
                t0 = gelu_exact(t0); t1 = gelu_exact(t1);
                t2 = gelu_exact(t2); t3 = gelu_exact(t3);
            }
            if (OUT == 0) {
                float* Cf = (float*)Co;
                float2 v0; v0.x = t0; v0.y = t1;
                float2 v1; v1.x = t2; v1.y = t3;
                *(float2*)(Cf + (size_t)r0 * N + col) = v0;
                *(float2*)(Cf + (size_t)r1 * N + col) = v1;
            } else {
                __half* Ch = (__half*)Co;
                *(__half2*)(Ch + (size_t)r0 * N + col) = __floats2half2_rn(t0, t1);
                *(__half2*)(Ch + (size_t)r1 * N + col) = __floats2half2_rn(t2, t3);
            }
        }
    }
}

// ===========================================================================
// Flash attention, fp16 m16n8k16 throughout. qkv is __half [tok][3C].
// 128 q rows/CTA (8 warps x 16), 64-key tiles double-buffered, pitch 72 h.
// ===========================================================================
constexpr int AQ   = 128;
constexpr int AKT  = 64;
constexpr int APiH = 72;
constexpr int A_KOFF = AQ * APiH;                   // halves
constexpr int A_VOFF = A_KOFF + 2 * AKT * APiH;
constexpr int ATT_SMEM = (A_VOFF + 2 * AKT * APiH) * 2;   // 55296 B

__global__ __launch_bounds__(256, 2)
void attn_h(const __half* __restrict__ qkv, __half* __restrict__ ctx)
{
    extern __shared__ __half smh[];
    __half* Qs = smh;
    __half* Ks = smh + A_KOFF;
    __half* Vs = smh + A_VOFF;
    const uint32_t Qs_u = smem_u32(Qs);
    const uint32_t Ks_u = smem_u32(Ks);
    const uint32_t Vs_u = smem_u32(Vs);

    const int tid = threadIdx.x;
    const int wid = tid >> 5;
    const int lid = tid & 31;
    const int g   = lid >> 2;
    const int tig = lid & 3;
    const int q0  = blockIdx.x * AQ;
    const int h   = blockIdx.y;
    const int b   = blockIdx.z;
    const int wq  = wid * 16;

    const size_t tok0 = (size_t)(b * Nn);
    const int hoff = h * HD;

    // ldmatrix lane addressing (byte offsets)
    const uint32_t q_lane = (uint32_t)((wq + (lid & 15)) * 144 + (lid >> 4) * 16);
    const uint32_t k_lane = (uint32_t)((lid & 7) * 144 + ((lid >> 3) & 1) * 16);
    const uint32_t v_lane = (uint32_t)((lid & 15) * 144);

    // Q tile: 128 rows x 8 chunks = 1024; 4/thread
    #pragma unroll
    for (int t = 0; t < 4; ++t) {
        int idx = tid + t * 256;
        int r = idx >> 3, c = idx & 7;
        cp_async16(Qs_u + (uint32_t)(r * 144 + c * 16),
                   qkv + (tok0 + q0 + r) * (3 * Cc_) + hoff + c * 8);
    }
    CP_COMMIT();

    auto load_tile = [&](int kt, int st) {
        const int k0 = kt * AKT;
        const uint32_t kb = Ks_u + (uint32_t)(st * AKT * APiH) * 2;
        const uint32_t vb = Vs_u + (uint32_t)(st * AKT * APiH) * 2;
        #pragma unroll
        for (int t = 0; t < 2; ++t) {
            int idx = tid + t * 256;
            int r = idx >> 3, c = idx & 7;
            const __half* src = qkv + (tok0 + k0 + r) * (3 * Cc_) + Cc_ + hoff + c * 8;
            uint32_t off = (uint32_t)(r * 144 + c * 16);
            cp_async16(kb + off, src);
            cp_async16(vb + off, src + Cc_);
        }
        CP_COMMIT();
    };
    load_tile(0, 0);
    load_tile(1, 1);

    CP_WAIT2();
    __syncthreads();

    // Q fragments: 4 chunks of K=16
    uint32_t qf[4][4];
    #pragma unroll
    for (int kk = 0; kk < 4; ++kk)
        LDSM4(qf[kk], Qs_u + q_lane + kk * 32);

    float o[8][4];
    #pragma unroll
    for (int d = 0; d < 8; ++d)
        #pragma unroll
        for (int t = 0; t < 4; ++t) o[d][t] = 0.f;
    float m0 = -1e30f, m1 = -1e30f, l0 = 0.f, l1 = 0.f;

    const int NT = Nn / AKT;     // 32
    for (int it = 0; it < NT; ++it) {
        const int st = it & 1;
        CP_WAIT1();
        __syncthreads();

        const uint32_t Kb = Ks_u + (uint32_t)(st * AKT * APiH) * 2;
        const uint32_t Vb = Vs_u + (uint32_t)(st * AKT * APiH) * 2;

        // ---- S = Q K^T  (8 key-chunks of 8) ----
        float s[8][4];
        #pragma unroll
        for (int nf = 0; nf < 8; ++nf) {
            s[nf][0] = 0.f; s[nf][1] = 0.f; s[nf][2] = 0.f; s[nf][3] = 0.f;
            const uint32_t kaddr = Kb + k_lane + nf * 8 * 144;
            #pragma unroll
            for (int kk = 0; kk < 4; ++kk) {
                uint32_t bf[2];
                LDSM2(bf, kaddr + kk * 32);
                mma_f16(s[nf], qf[kk], bf);
            }
            s[nf][0] *= SCALE; s[nf][1] *= SCALE;
            s[nf][2] *= SCALE; s[nf][3] *= SCALE;
        }

        // ---- softmax update ----
        float t0 = -1e30f, t1 = -1e30f;
        #pragma unroll
        for (int nf = 0; nf < 8; ++nf) {
            t0 = fmaxf(t0, fmaxf(s[nf][0], s[nf][1]));
            t1 = fmaxf(t1, fmaxf(s[nf][2], s[nf][3]));
        }
        t0 = fmaxf(t0, __shfl_xor_sync(0xffffffff, t0, 1));
        t0 = fmaxf(t0, __shfl_xor_sync(0xffffffff, t0, 2));
        t1 = fmaxf(t1, __shfl_xor_sync(0xffffffff, t1, 1));
        t1 = fmaxf(t1, __shfl_xor_sync(0xffffffff, t1, 2));
        const float nm0 = fmaxf(m0, t0), nm1 = fmaxf(m1, t1);
        const float c0 = __expf(m0 - nm0), c1 = __expf(m1 - nm1);
        m0 = nm0; m1 = nm1;
        l0 *= c0; l1 *= c1;
        #pragma unroll
        for (int d = 0; d < 8; ++d) {
            o[d][0] *= c0; o[d][1] *= c0;
            o[d][2] *= c1; o[d][3] *= c1;
        }

        // ---- P = exp(S-m) packed directly into k16 A-fragments ----
        uint32_t pa[4][4];
        #pragma unroll
        for (int nf = 0; nf < 8; ++nf) {
            float p0 = __expf(s[nf][0] - m0);
            float p1 = __expf(s[nf][1] - m0);
            float p2 = __expf(s[nf][2] - m1);
            float p3 = __expf(s[nf][3] - m1);
            l0 += p0 + p1;
            l1 += p2 + p3;
            pa[nf >> 1][2 * (nf & 1) + 0] = h2_as_u32(__floats2half2_rn(p0, p1));
            pa[nf >> 1][2 * (nf & 1) + 1] = h2_as_u32(__floats2half2_rn(p2, p3));
        }

        // ---- O += P V  (V^T fragments via ldmatrix.trans) ----
        #pragma unroll
        for (int kt2 = 0; kt2 < 4; ++kt2) {
            const uint32_t vbase = Vb + v_lane + kt2 * 16 * 144;
            #pragma unroll
            for (int df = 0; df < 8; ++df) {
                uint32_t bf[2];
                LDSM2T(bf, vbase + df * 16);
                mma_f16(o[df], pa[kt2], bf);
            }
        }

        __syncthreads();
        if (it + 2 < NT) load_tile(it + 2, st);
        else             CP_COMMIT();
    }

    l0 += __shfl_xor_sync(0xffffffff, l0, 1);
    l0 += __shfl_xor_sync(0xffffffff, l0, 2);
    l1 += __shfl_xor_sync(0xffffffff, l1, 1);
    l1 += __shfl_xor_sync(0xffffffff, l1, 2);
    const float inv0 = 1.f / l0, inv1 = 1.f / l1;
    const int qr0 = q0 + wq + g;
    const int qr1 = qr0 + 8;
    #pragma unroll
    for (int df = 0; df < 8; ++df) {
        *(__half2*)(ctx + (tok0 + qr0) * Cc_ + hoff + 8 * df + 2 * tig) =
            __floats2half2_rn(o[df][0] * inv0, o[df][1] * inv0);
        *(__half2*)(ctx + (tok0 + qr1) * Cc_ + hoff + 8 * df + 2 * tig) =
            __floats2half2_rn(o[df][2] * inv1, o[df][3] * inv1);
    }
}

// ---------------------------------------------------------------------------
// out[row] = res[row] + LayerNorm(x[row]) * w + b     (row length 1024)
// DUAL=1: also write __half copy to out_h.
// ---------------------------------------------------------------------------
template<int DUAL>
__global__ __launch_bounds__(256)
void ln_residual(const float* __restrict__ x, const float* __restrict__ res,
                 const float* __restrict__ w, const float* __restrict__ bp,
                 float* __restrict__ out, __half* __restrict__ out_h)
{
    __shared__ float red[256];
    const int row = blockIdx.x;
    const int tid = threadIdx.x;
    const size_t base = (size_t)row * Cc_;

    float4 v = *(const float4*)(x + base + tid * 4);
    float s = v.x + v.y + v.z + v.w;
    red[tid] = s;
    __syncthreads();
    #pragma unroll
    for (int off = 128; off > 0; off >>= 1) {
        if (tid < off) red[tid] += red[tid + off];
        __syncthreads();
    }
    const float mu = red[0] * (1.0f / Cc_);
    __syncthreads();

    float d0 = v.x - mu, d1 = v.y - mu, d2 = v.z - mu, d3 = v.w - mu;
    red[tid] = d0*d0 + d1*d1 + d2*d2 + d3*d3;
    __syncthreads();
    #pragma unroll
    for (int off = 128; off > 0; off >>= 1) {
        if (tid < off) red[tid] += red[tid + off];
        __syncthreads();
    }
    const float var  = red[0] * (1.0f / Cc_);
    const float rstd = rsqrtf(var + 1e-5f);

    float4 rv = *(const float4*)(res + base + tid * 4);
    float4 wv = *(const float4*)(w + tid * 4);
    float4 bv = *(const float4*)(bp + tid * 4);
    float4 ov;
    ov.x = rv.x + d0 * rstd * wv.x + bv.x;
    ov.y = rv.y + d1 * rstd * wv.y + bv.y;
    ov.z = rv.z + d2 * rstd * wv.z + bv.z;
    ov.w = rv.w + d3 * rstd * wv.w + bv.w;
    *(float4*)(out + base + tid * 4) = ov;
    if (DUAL == 1) {
        __half2* oh = (__half2*)(out_h + base + tid * 4);
        oh[0] = __floats2half2_rn(ov.x, ov.y);
        oh[1] = __floats2half2_rn(ov.z, ov.w);
    }
}

// ---------------------------------------------------------------------------
// Launch
// ---------------------------------------------------------------------------
extern "C" void kernel_launch(void* const* d_in, const int* in_sizes, int n_in,
                              void* d_out, int out_size)
{
    const float* x      = (const float*)d_in[0];
    const float* qkv_w  = (const float*)d_in[1];
    const float* proj_w = (const float*)d_in[2];
    const float* proj_b = (const float*)d_in[3];
    const float* ln1_w  = (const float*)d_in[4];
    const float* ln1_b  = (const float*)d_in[5];
    const float* fc1_w  = (const float*)d_in[6];
    const float* fc1_b  = (const float*)d_in[7];
    const float* fc2_w  = (const float*)d_in[8];
    const float* fc2_b  = (const float*)d_in[9];
    const float* ln2_w  = (const float*)d_in[10];
    const float* ln2_b  = (const float*)d_in[11];
    float* out = (float*)d_out;

    float *res, *mlp;
    __half *qkv, *ctx, *resr, *hbuf, *xh, *w1, *w2, *w3, *w4;
    cudaGetSymbolAddress((void**)&qkv,  g_qkv);
    cudaGetSymbolAddress((void**)&ctx,  g_ctx);
    cudaGetSymbolAddress((void**)&res,  g_res);
    cudaGetSymbolAddress((void**)&resr, g_resr);
    cudaGetSymbolAddress((void**)&hbuf, g_h);
    cudaGetSymbolAddress((void**)&mlp,  g_mlp);
    cudaGetSymbolAddress((void**)&xh,   g_xh);
    cudaGetSymbolAddress((void**)&w1,   g_w1);
    cudaGetSymbolAddress((void**)&w2,   g_w2);
    cudaGetSymbolAddress((void**)&w3,   g_w3);
    cudaGetSymbolAddress((void**)&w4,   g_w4);

    cudaFuncSetAttribute(h_gemm<0,0>,
        cudaFuncAttributeMaxDynamicSharedMemorySize, GEMM_SMEM);
    cudaFuncSetAttribute(h_gemm<0,2>,
        cudaFuncAttributeMaxDynamicSharedMemorySize, GEMM_SMEM);
    cudaFuncSetAttribute(h_gemm<1,2>,
        cudaFuncAttributeMaxDynamicSharedMemorySize, GEMM_SMEM);
    cudaFuncSetAttribute(attn_h,
        cudaFuncAttributeMaxDynamicSharedMemorySize, ATT_SMEM);

    // 0) one fused fp16 conversion pass for all GEMM operands
    to_half_all<<<CONV_BLOCKS, 256>>>(x, qkv_w, proj_w, fc1_w, fc2_w,
                                      xh, w1, w2, w3, w4);

    // 1) qkv = x @ qkv_w^T  (half out)
    h_gemm<0,2><<<dim3(3 * Cc_ / GBN, MTOK / GBM), 256, GEMM_SMEM>>>(
        xh, w1, nullptr, qkv, MTOK, 3 * Cc_, Cc_);
    // 2) attention -> ctx (half)
    attn_h<<<dim3(Nn / AQ, Hh, Bb), 256, ATT_SMEM>>>(qkv, ctx);
    // 3) res = ctx @ proj_w^T + proj_b  (fp32 residual base)
    h_gemm<0,0><<<dim3(Cc_ / GBN, MTOK / GBM), 256, GEMM_SMEM>>>(
        ctx, w2, proj_b, res, MTOK, Cc_, Cc_);
    // 4) res = res + LN(res); also half copy resr
    ln_residual<1><<<MTOK, 256>>>(res, res, ln1_w, ln1_b, res, resr);
    // 5) h = gelu(resr @ fc1_w^T + fc1_b)  (half out)
    h_gemm<1,2><<<dim3(HID / GBN, MTOK / GBM), 256, GEMM_SMEM>>>(
        resr, w3, fc1_b, hbuf, MTOK, HID, Cc_);
    // 6) mlp = h @ fc2_w^T + fc2_b  (fp32 out)
    h_gemm<0,0><<<dim3(Cc_ / GBN, MTOK / GBM), 256, GEMM_SMEM>>>(
        hbuf, w4, fc2_b, mlp, MTOK, Cc_, HID);
    // 7) out = res + LN(mlp)
    ln_residual<0><<<MTOK, 256>>>(mlp, res, ln2_w, ln2_b, out, nullptr);
}

// round 12
// speedup vs baseline: 7.3548x; 1.0238x over previous
#include <cuda_runtime.h>
#include <cuda_fp16.h>
#include <math.h>
#include <stdint.h>

// Problem constants
constexpr int Bb   = 2;
constexpr int Nn   = 2048;
constexpr int Cc_  = 1024;
constexpr int Hh   = 16;
constexpr int HD   = 64;
constexpr int HID  = 4096;
constexpr int MTOK = Bb * Nn;            // 4096 token rows
constexpr float SCALE = 0.125f;          // 64^-0.5

// Scratch (static device allocations; no cudaMalloc allowed)
__device__ __half g_qkv [(size_t)MTOK * 3 * Cc_];   // 24 MB
__device__ __half g_ctx [(size_t)MTOK * Cc_];       //  8 MB
__device__ float  g_res [(size_t)MTOK * Cc_];       // 16 MB fp32 residual
__device__ __half g_resr[(size_t)MTOK * Cc_];       //  8 MB half copy
__device__ __half g_h   [(size_t)MTOK * HID];       // 32 MB
__device__ float  g_mlp [(size_t)MTOK * Cc_];       // 16 MB fp32
__device__ __half g_xh  [(size_t)MTOK * Cc_];       //  8 MB half x
__device__ __half g_w1  [(size_t)3 * Cc_ * Cc_];    //  6 MB
__device__ __half g_w2  [(size_t)Cc_ * Cc_];        //  2 MB
__device__ __half g_w3  [(size_t)HID * Cc_];        //  8 MB
__device__ __half g_w4  [(size_t)Cc_ * HID];        //  8 MB

// ===========================================================================
// helpers
// ===========================================================================
__device__ __forceinline__ uint32_t smem_u32(const void* p) {
    uint32_t a;
    asm("{ .reg .u64 t; cvta.to.shared.u64 t, %1; cvt.u32.u64 %0, t; }"
        : "=r"(a) : "l"(p));
    return a;
}
__device__ __forceinline__ void cp_async16(uint32_t dst, const void* src) {
    asm volatile("cp.async.cg.shared.global [%0], [%1], 16;"
                 :: "r"(dst), "l"(src));
}
#define CP_COMMIT() asm volatile("cp.async.commit_group;" ::: "memory")
#define CP_WAIT1()  asm volatile("cp.async.wait_group 1;" ::: "memory")
#define CP_WAIT2()  asm volatile("cp.async.wait_group 2;" ::: "memory")

#define LDSM4(r, a) \
    asm volatile("ldmatrix.sync.aligned.m8n8.x4.shared.b16 {%0,%1,%2,%3}, [%4];" \
        : "=r"((r)[0]), "=r"((r)[1]), "=r"((r)[2]), "=r"((r)[3]) : "r"(a))
#define LDSM2(r, a) \
    asm volatile("ldmatrix.sync.aligned.m8n8.x2.shared.b16 {%0,%1}, [%2];" \
        : "=r"((r)[0]), "=r"((r)[1]) : "r"(a))
#define LDSM2T(r, a) \
    asm volatile("ldmatrix.sync.aligned.m8n8.x2.trans.shared.b16 {%0,%1}, [%2];" \
        : "=r"((r)[0]), "=r"((r)[1]) : "r"(a))

// bit-reinterpret __half2 -> uint32_t (compiles to nothing)
__device__ __forceinline__ uint32_t h2_as_u32(__half2 h) {
    uint32_t u;
    *reinterpret_cast<__half2*>(&u) = h;
    return u;
}

// mma.sync m16n8k16 f16, fp32 accumulate
__device__ __forceinline__ void mma_f16(float* c, const uint32_t* a,
                                        const uint32_t* b) {
    asm volatile(
        "mma.sync.aligned.m16n8k16.row.col.f32.f16.f16.f32 "
        "{%0,%1,%2,%3}, {%4,%5,%6,%7}, {%8,%9}, {%0,%1,%2,%3};"
        : "+f"(c[0]), "+f"(c[1]), "+f"(c[2]), "+f"(c[3])
        : "r"(a[0]), "r"(a[1]), "r"(a[2]), "r"(a[3]),
          "r"(b[0]), "r"(b[1]));
}

__device__ __forceinline__ float gelu_exact(float v) {
    return 0.5f * v * (1.0f + erff(v * 0.70710678118654752f));
}

// ---------------------------------------------------------------------------
// Fused fp16 conversion: all 5 operand tensors in ONE launch.
// ---------------------------------------------------------------------------
constexpr int C4_X  = MTOK * Cc_ / 4;          // 1048576
constexpr int C4_W1 = 3 * Cc_ * Cc_ / 4;       //  786432
constexpr int C4_W2 = Cc_ * Cc_ / 4;           //  262144
constexpr int C4_W3 = HID * Cc_ / 4;           // 1048576
constexpr int C4_W4 = C4_W3;                   // 1048576
constexpr int C4_B0 = C4_X;
constexpr int C4_B1 = C4_B0 + C4_W1;
constexpr int C4_B2 = C4_B1 + C4_W2;
constexpr int C4_B3 = C4_B2 + C4_W3;
constexpr int C4_TOT = C4_B3 + C4_W4;          // 4194304
constexpr int CONV_BLOCKS = C4_TOT / 2 / 256;  // 8192

__global__ __launch_bounds__(256)
void to_half_all(const float* __restrict__ x,  const float* __restrict__ a1,
                 const float* __restrict__ a2, const float* __restrict__ a3,
                 const float* __restrict__ a4,
                 __half* __restrict__ xo, __half* __restrict__ o1,
                 __half* __restrict__ o2, __half* __restrict__ o3,
                 __half* __restrict__ o4)
{
    const int i8 = blockIdx.x * 256 + threadIdx.x;   // 8-float unit
    const int i4 = i8 * 2;                           // float4 unit (even)
    const float* src; __half* dst; int off4;
    if (i4 < C4_B0)      { src = x;  dst = xo; off4 = i4; }
    else if (i4 < C4_B1) { src = a1; dst = o1; off4 = i4 - C4_B0; }
    else if (i4 < C4_B2) { src = a2; dst = o2; off4 = i4 - C4_B1; }
    else if (i4 < C4_B3) { src = a3; dst = o3; off4 = i4 - C4_B2; }
    else                 { src = a4; dst = o4; off4 = i4 - C4_B3; }
    float4 v0 = ((const float4*)src)[off4];
    float4 v1 = ((const float4*)src)[off4 + 1];
    __half2 h[4];
    h[0] = __floats2half2_rn(v0.x, v0.y);
    h[1] = __floats2half2_rn(v0.z, v0.w);
    h[2] = __floats2half2_rn(v1.x, v1.y);
    h[3] = __floats2half2_rn(v1.z, v1.w);
    *(uint4*)((__half2*)dst + off4 * 2) = *(uint4*)h;
}

// ===========================================================================
// fp16 mma.sync GEMM (NT), ldmatrix fragment loads.
// ONE-barrier 3-slot pipeline: 2 cp.async groups in flight, loads issued
// BEFORE compute each iteration (slot written was last read 1 iter ago,
// ordered by this iteration's single barrier).
// BM=BN=128, BK=64 halves, 256 threads (8 warps 2x4), warp tile 64x32,
// pitch 72 halves (144B). OUT: 0 = f32, 2 = f16.
// ===========================================================================
constexpr int GBM = 128, GBN = 128, HBK = 64;
constexpr int HPITCH = HBK + 8;                     // 72 halves = 144 B
constexpr int STAGE_H = GBM * HPITCH;               // halves per operand stage
constexpr int NSTG = 3;
constexpr int GEMM_SMEM = NSTG * 2 * STAGE_H * 2;   // 110592 B

template<int EPI, int OUT>
__global__ __launch_bounds__(256, 2)
void h_gemm(const __half* __restrict__ A, const __half* __restrict__ Bw,
            const float* __restrict__ bias, void* __restrict__ Co,
            int M, int N, int K)
{
    extern __shared__ __half smemh[];
    __half* As = smemh;
    __half* Bs = smemh + NSTG * STAGE_H;
    const uint32_t As_u = smem_u32(As);
    const uint32_t Bs_u = smem_u32(Bs);

    const int tid = threadIdx.x;
    const int wid = tid >> 5;
    const int lid = tid & 31;
    const int g   = lid >> 2;
    const int tig = lid & 3;
    const int wm  = (wid & 1) * 64;
    const int wn  = (wid >> 1) * 32;
    const int m0  = blockIdx.y * GBM;
    const int n0  = blockIdx.x * GBN;
    const int NC  = K / HBK;

    // ldmatrix lane addressing (byte offsets within a stage)
    const uint32_t a_lane = (uint32_t)((wm + (lid & 15)) * 144 + (lid >> 4) * 16);
    const uint32_t b_lane = (uint32_t)((wn + (lid & 7)) * 144 + ((lid >> 3) & 1) * 16);

    float acc[4][4][4];
    #pragma unroll
    for (int i = 0; i < 4; ++i)
        #pragma unroll
        for (int j = 0; j < 4; ++j)
            #pragma unroll
            for (int t = 0; t < 4; ++t) acc[i][j][t] = 0.f;

    auto load_chunk = [&](int kc, int st) {
        const int k0h = kc * HBK;
        const uint32_t abase = As_u + st * STAGE_H * 2;
        const uint32_t bbase = Bs_u + st * STAGE_H * 2;
        #pragma unroll
        for (int t = 0; t < 4; ++t) {
            int idx = tid + t * 256;
            int r   = idx >> 3;
            int c   = idx & 7;
            uint32_t off = (uint32_t)(r * 144 + c * 16);
            cp_async16(abase + off, A + (size_t)(m0 + r) * K + k0h + c * 8);
            cp_async16(bbase + off, Bw + (size_t)(n0 + r) * K + k0h + c * 8);
        }
        CP_COMMIT();
    };

    // preload 2 chunks (2 groups in flight)
    load_chunk(0, 0);
    load_chunk(1, 1);

    int cst = 0;   // consume slot
    int lst = 2;   // load slot
    for (int i = 0; i < NC; ++i) {
        CP_WAIT1();             // chunk i resident
        __syncthreads();        // orders prior iter's reads before slot reuse

        // issue next loads FIRST (overlap DMA with MMA below)
        if (i + 2 < NC) load_chunk(i + 2, lst);
        else            CP_COMMIT();
        lst = (lst == NSTG - 1) ? 0 : lst + 1;

        const uint32_t Ast = As_u + cst * STAGE_H * 2;
        const uint32_t Bst = Bs_u + cst * STAGE_H * 2;

        #pragma unroll
        for (int kk = 0; kk < 4; ++kk) {           // 4 x K=16
            uint32_t af[4][4], bf[4][2];
            #pragma unroll
            for (int mf = 0; mf < 4; ++mf)
                LDSM4(af[mf], Ast + a_lane + mf * 16 * 144 + kk * 32);
            #pragma unroll
            for (int nf = 0; nf < 4; ++nf)
                LDSM2(bf[nf], Bst + b_lane + nf * 8 * 144 + kk * 32);
            #pragma unroll
            for (int mf = 0; mf < 4; ++mf)
                #pragma unroll
                for (int nf = 0; nf < 4; ++nf)
                    mma_f16(acc[mf][nf], af[mf], bf[nf]);
        }

        cst = (cst == NSTG - 1) ? 0 : cst + 1;
    }

    #pragma unroll
    for (int mf = 0; mf < 4; ++mf) {
        const int r0 = m0 + wm + mf * 16 + g;
        const int r1 = r0 + 8;
        #pragma unroll
        for (int nf = 0; nf < 4; ++nf) {
            const int col = n0 + wn + nf * 8 + tig * 2;
            float b0 = 0.f, b1 = 0.f;
            if (bias) { b0 = bias[col]; b1 = bias[col + 1]; }
            float t0 = acc[mf][nf][0] + b0;
            float t1 = acc[mf][nf][1] + b1;
            float t2 = acc[mf][nf][2] + b0;
            float t3 = acc[mf][nf][3] + b1;
            if (EPI == 1) {
                t0 = gelu_exact(t0); t1 = gelu_exact(t1);
                t2 = gelu_exact(t2); t3 = gelu_exact(t3);
            }
            if (OUT == 0) {
                float* Cf = (float*)Co;
                float2 v0; v0.x = t0; v0.y = t1;
                float2 v1; v1.x = t2; v1.y = t3;
                *(float2*)(Cf + (size_t)r0 * N + col) = v0;
                *(float2*)(Cf + (size_t)r1 * N + col) = v1;
            } else {
                __half* Ch = (__half*)Co;
                *(__half2*)(Ch + (size_t)r0 * N + col) = __floats2half2_rn(t0, t1);
                *(__half2*)(Ch + (size_t)r1 * N + col) = __floats2half2_rn(t2, t3);
            }
        }
    }
}

// ===========================================================================
// Flash attention, fp16 m16n8k16, same one-barrier 3-slot K/V pipeline.
// 128 q rows/CTA (8 warps x 16), 64-key tiles, pitch 72 halves.
// ===========================================================================
constexpr int AQ   = 128;
constexpr int AKT  = 64;
constexpr int APiH = 72;
constexpr int A_KOFF = AQ * APiH;                    // halves
constexpr int A_VOFF = A_KOFF + 3 * AKT * APiH;
constexpr int ATT_SMEM = (A_VOFF + 3 * AKT * APiH) * 2;   // 73728 B

__global__ __launch_bounds__(256, 2)
void attn_h(const __half* __restrict__ qkv, __half* __restrict__ ctx)
{
    extern __shared__ __half smh[];
    __half* Qs = smh;
    __half* Ks = smh + A_KOFF;
    __half* Vs = smh + A_VOFF;
    const uint32_t Qs_u = smem_u32(Qs);
    const uint32_t Ks_u = smem_u32(Ks);
    const uint32_t Vs_u = smem_u32(Vs);

    const int tid = threadIdx.x;
    const int wid = tid >> 5;
    const int lid = tid & 31;
    const int g   = lid >> 2;
    const int tig = lid & 3;
    const int q0  = blockIdx.x * AQ;
    const int h   = blockIdx.y;
    const int b   = blockIdx.z;
    const int wq  = wid * 16;

    const size_t tok0 = (size_t)(b * Nn);
    const int hoff = h * HD;

    // ldmatrix lane addressing (byte offsets)
    const uint32_t q_lane = (uint32_t)((wq + (lid & 15)) * 144 + (lid >> 4) * 16);
    const uint32_t k_lane = (uint32_t)((lid & 7) * 144 + ((lid >> 3) & 1) * 16);
    const uint32_t v_lane = (uint32_t)((lid & 15) * 144);

    // Q tile: 128 rows x 8 chunks = 1024; 4/thread  (own cp.async group)
    #pragma unroll
    for (int t = 0; t < 4; ++t) {
        int idx = tid + t * 256;
        int r = idx >> 3, c = idx & 7;
        cp_async16(Qs_u + (uint32_t)(r * 144 + c * 16),
                   qkv + (tok0 + q0 + r) * (3 * Cc_) + hoff + c * 8);
    }
    CP_COMMIT();

    auto load_tile = [&](int kt, int st) {
        const int k0 = kt * AKT;
        const uint32_t kb = Ks_u + (uint32_t)(st * AKT * APiH) * 2;
        const uint32_t vb = Vs_u + (uint32_t)(st * AKT * APiH) * 2;
        #pragma unroll
        for (int t = 0; t < 2; ++t) {
            int idx = tid + t * 256;
            int r = idx >> 3, c = idx & 7;
            const __half* src = qkv + (tok0 + k0 + r) * (3 * Cc_) + Cc_ + hoff + c * 8;
            uint32_t off = (uint32_t)(r * 144 + c * 16);
            cp_async16(kb + off, src);
            cp_async16(vb + off, src + Cc_);
        }
        CP_COMMIT();
    };
    load_tile(0, 0);
    load_tile(1, 1);

    CP_WAIT2();            // Q resident (tiles 0,1 may be in flight)
    __syncthreads();

    // Q fragments: 4 chunks of K=16
    uint32_t qf[4][4];
    #pragma unroll
    for (int kk = 0; kk < 4; ++kk)
        LDSM4(qf[kk], Qs_u + q_lane + kk * 32);

    float o[8][4];
    #pragma unroll
    for (int d = 0; d < 8; ++d)
        #pragma unroll
        for (int t = 0; t < 4; ++t) o[d][t] = 0.f;
    float m0 = -1e30f, m1 = -1e30f, l0 = 0.f, l1 = 0.f;

    const int NT = Nn / AKT;     // 32
    int cst = 0, lst = 2;
    for (int it = 0; it < NT; ++it) {
        CP_WAIT1();
        __syncthreads();

        if (it + 2 < NT) load_tile(it + 2, lst);
        else             CP_COMMIT();
        lst = (lst == 2) ? 0 : lst + 1;

        const uint32_t Kb = Ks_u + (uint32_t)(cst * AKT * APiH) * 2;
        const uint32_t Vb = Vs_u + (uint32_t)(cst * AKT * APiH) * 2;

        // ---- S = Q K^T  (8 key-chunks of 8) ----
        float s[8][4];
        #pragma unroll
        for (int nf = 0; nf < 8; ++nf) {
            s[nf][0] = 0.f; s[nf][1] = 0.f; s[nf][2] = 0.f; s[nf][3] = 0.f;
            const uint32_t kaddr = Kb + k_lane + nf * 8 * 144;
            #pragma unroll
            for (int kk = 0; kk < 4; ++kk) {
                uint32_t bf[2];
                LDSM2(bf, kaddr + kk * 32);
                mma_f16(s[nf], qf[kk], bf);
            }
            s[nf][0] *= SCALE; s[nf][1] *= SCALE;
            s[nf][2] *= SCALE; s[nf][3] *= SCALE;
        }

        // ---- softmax update ----
        float t0 = -1e30f, t1 = -1e30f;
        #pragma unroll
        for (int nf = 0; nf < 8; ++nf) {
            t0 = fmaxf(t0, fmaxf(s[nf][0], s[nf][1]));
            t1 = fmaxf(t1, fmaxf(s[nf][2], s[nf][3]));
        }
        t0 = fmaxf(t0, __shfl_xor_sync(0xffffffff, t0, 1));
        t0 = fmaxf(t0, __shfl_xor_sync(0xffffffff, t0, 2));
        t1 = fmaxf(t1, __shfl_xor_sync(0xffffffff, t1, 1));
        t1 = fmaxf(t1, __shfl_xor_sync(0xffffffff, t1, 2));
        const float nm0 = fmaxf(m0, t0), nm1 = fmaxf(m1, t1);
        const float c0 = __expf(m0 - nm0), c1 = __expf(m1 - nm1);
        m0 = nm0; m1 = nm1;
        l0 *= c0; l1 *= c1;
        #pragma unroll
        for (int d = 0; d < 8; ++d) {
            o[d][0] *= c0; o[d][1] *= c0;
            o[d][2] *= c1; o[d][3] *= c1;
        }

        // ---- P = exp(S-m) packed directly into k16 A-fragments ----
        uint32_t pa[4][4];
        #pragma unroll
        for (int nf = 0; nf < 8; ++nf) {
            float p0 = __expf(s[nf][0] - m0);
            float p1 = __expf(s[nf][1] - m0);
            float p2 = __expf(s[nf][2] - m1);
            float p3 = __expf(s[nf][3] - m1);
            l0 += p0 + p1;
            l1 += p2 + p3;
            pa[nf >> 1][2 * (nf & 1) + 0] = h2_as_u32(__floats2half2_rn(p0, p1));
            pa[nf >> 1][2 * (nf & 1) + 1] = h2_as_u32(__floats2half2_rn(p2, p3));
        }

        // ---- O += P V  (V^T fragments via ldmatrix.trans) ----
        #pragma unroll
        for (int kt2 = 0; kt2 < 4; ++kt2) {
            const uint32_t vbase = Vb + v_lane + kt2 * 16 * 144;
            #pragma unroll
            for (int df = 0; df < 8; ++df) {
                uint32_t bf[2];
                LDSM2T(bf, vbase + df * 16);
                mma_f16(o[df], pa[kt2], bf);
            }
        }

        cst = (cst == 2) ? 0 : cst + 1;
    }

    l0 += __shfl_xor_sync(0xffffffff, l0, 1);
    l0 += __shfl_xor_sync(0xffffffff, l0, 2);
    l1 += __shfl_xor_sync(0xffffffff, l1, 1);
    l1 += __shfl_xor_sync(0xffffffff, l1, 2);
    const float inv0 = 1.f / l0, inv1 = 1.f / l1;
    const int qr0 = q0 + wq + g;
    const int qr1 = qr0 + 8;
    #pragma unroll
    for (int df = 0; df < 8; ++df) {
        *(__half2*)(ctx + (tok0 + qr0) * Cc_ + hoff + 8 * df + 2 * tig) =
            __floats2half2_rn(o[df][0] * inv0, o[df][1] * inv0);
        *(__half2*)(ctx + (tok0 + qr1) * Cc_ + hoff + 8 * df + 2 * tig) =
            __floats2half2_rn(o[df][2] * inv1, o[df][3] * inv1);
    }
}

// ---------------------------------------------------------------------------
// out[row] = res[row] + LayerNorm(x[row]) * w + b     (row length 1024)
// DUAL=1: also write __half copy to out_h.
// ---------------------------------------------------------------------------
template<int DUAL>
__global__ __launch_bounds__(256)
void ln_residual(const float* __restrict__ x, const float* __restrict__ res,
                 const float* __restrict__ w, const float* __restrict__ bp,
                 float* __restrict__ out, __half* __restrict__ out_h)
{
    __shared__ float red[256];
    const int row = blockIdx.x;
    const int tid = threadIdx.x;
    const size_t base = (size_t)row * Cc_;

    float4 v = *(const float4*)(x + base + tid * 4);
    float s = v.x + v.y + v.z + v.w;
    red[tid] = s;
    __syncthreads();
    #pragma unroll
    for (int off = 128; off > 0; off >>= 1) {
        if (tid < off) red[tid] += red[tid + off];
        __syncthreads();
    }
    const float mu = red[0] * (1.0f / Cc_);
    __syncthreads();

    float d0 = v.x - mu, d1 = v.y - mu, d2 = v.z - mu, d3 = v.w - mu;
    red[tid] = d0*d0 + d1*d1 + d2*d2 + d3*d3;
    __syncthreads();
    #pragma unroll
    for (int off = 128; off > 0; off >>= 1) {
        if (tid < off) red[tid] += red[tid + off];
        __syncthreads();
    }
    const float var  = red[0] * (1.0f / Cc_);
    const float rstd = rsqrtf(var + 1e-5f);

    float4 rv = *(const float4*)(res + base + tid * 4);
    float4 wv = *(const float4*)(w + tid * 4);
    float4 bv = *(const float4*)(bp + tid * 4);
    float4 ov;
    ov.x = rv.x + d0 * rstd * wv.x + bv.x;
    ov.y = rv.y + d1 * rstd * wv.y + bv.y;
    ov.z = rv.z + d2 * rstd * wv.z + bv.z;
    ov.w = rv.w + d3 * rstd * wv.w + bv.w;
    *(float4*)(out + base + tid * 4) = ov;
    if (DUAL == 1) {
        __half2* oh = (__half2*)(out_h + base + tid * 4);
        oh[0] = __floats2half2_rn(ov.x, ov.y);
        oh[1] = __floats2half2_rn(ov.z, ov.w);
    }
}

// ---------------------------------------------------------------------------
// Launch
// ---------------------------------------------------------------------------
extern "C" void kernel_launch(void* const* d_in, const int* in_sizes, int n_in,
                              void* d_out, int out_size)
{
    const float* x      = (const float*)d_in[0];
    const float* qkv_w  = (const float*)d_in[1];
    const float* proj_w = (const float*)d_in[2];
    const float* proj_b = (const float*)d_in[3];
    const float* ln1_w  = (const float*)d_in[4];
    const float* ln1_b  = (const float*)d_in[5];
    const float* fc1_w  = (const float*)d_in[6];
    const float* fc1_b  = (const float*)d_in[7];
    const float* fc2_w  = (const float*)d_in[8];
    const float* fc2_b  = (const float*)d_in[9];
    const float* ln2_w  = (const float*)d_in[10];
    const float* ln2_b  = (const float*)d_in[11];
    float* out = (float*)d_out;

    float *res, *mlp;
    __half *qkv, *ctx, *resr, *hbuf, *xh, *w1, *w2, *w3, *w4;
    cudaGetSymbolAddress((void**)&qkv,  g_qkv);
    cudaGetSymbolAddress((void**)&ctx,  g_ctx);
    cudaGetSymbolAddress((void**)&res,  g_res);
    cudaGetSymbolAddress((void**)&resr, g_resr);
    cudaGetSymbolAddress((void**)&hbuf, g_h);
    cudaGetSymbolAddress((void**)&mlp,  g_mlp);
    cudaGetSymbolAddress((void**)&xh,   g_xh);
    cudaGetSymbolAddress((void**)&w1,   g_w1);
    cudaGetSymbolAddress((void**)&w2,   g_w2);
    cudaGetSymbolAddress((void**)&w3,   g_w3);
    cudaGetSymbolAddress((void**)&w4,   g_w4);

    cudaFuncSetAttribute(h_gemm<0,0>,
        cudaFuncAttributeMaxDynamicSharedMemorySize, GEMM_SMEM);
    cudaFuncSetAttribute(h_gemm<0,2>,
        cudaFuncAttributeMaxDynamicSharedMemorySize, GEMM_SMEM);
    cudaFuncSetAttribute(h_gemm<1,2>,
        cudaFuncAttributeMaxDynamicSharedMemorySize, GEMM_SMEM);
    cudaFuncSetAttribute(attn_h,
        cudaFuncAttributeMaxDynamicSharedMemorySize, ATT_SMEM);

    // 0) one fused fp16 conversion pass for all GEMM operands
    to_half_all<<<CONV_BLOCKS, 256>>>(x, qkv_w, proj_w, fc1_w, fc2_w,
                                      xh, w1, w2, w3, w4);

    // 1) qkv = x @ qkv_w^T  (half out)
    h_gemm<0,2><<<dim3(3 * Cc_ / GBN, MTOK / GBM), 256, GEMM_SMEM>>>(
        xh, w1, nullptr, qkv, MTOK, 3 * Cc_, Cc_);
    // 2) attention -> ctx (half)
    attn_h<<<dim3(Nn / AQ, Hh, Bb), 256, ATT_SMEM>>>(qkv, ctx);
    // 3) res = ctx @ proj_w^T + proj_b  (fp32 residual base)
    h_gemm<0,0><<<dim3(Cc_ / GBN, MTOK / GBM), 256, GEMM_SMEM>>>(
        ctx, w2, proj_b, res, MTOK, Cc_, Cc_);
    // 4) res = res + LN(res); also half copy resr
    ln_residual<1><<<MTOK, 256>>>(res, res, ln1_w, ln1_b, res, resr);
    // 5) h = gelu(resr @ fc1_w^T + fc1_b)  (half out)
    h_gemm<1,2><<<dim3(HID / GBN, MTOK / GBM), 256, GEMM_SMEM>>>(
        resr, w3, fc1_b, hbuf, MTOK, HID, Cc_);
    // 6) mlp = h @ fc2_w^T + fc2_b  (fp32 out)
    h_gemm<0,0><<<dim3(Cc_ / GBN, MTOK / GBM), 256, GEMM_SMEM>>>(
        hbuf, w4, fc2_b, mlp, MTOK, Cc_, HID);
    // 7) out = res + LN(mlp)
    ln_residual<0><<<MTOK, 256>>>(mlp, res, ln2_w, ln2_b, out, nullptr);
}